// round 1
// baseline (speedup 1.0000x reference)
#include <cuda_runtime.h>
#include <cstdint>
#include <math_constants.h>

// ---------------- problem-size capacities (fixed by the dataset) -------------
#define NMAX 20000
#define EMAX 30000
#define BMAX 128
#define DIM  64

// ---------------- device scratch (static: no allocations allowed) ------------
__device__ float g_h[NMAX * DIM];            // node hidden state (== feat)
__device__ float g_agg[NMAX * DIM];          // message aggregate
__device__ float g_m[NMAX * DIM];            // GRU input m
__device__ float g_ahid[EMAX * 128];         // ENN hidden
__device__ float g_ew[(size_t)EMAX * 4096];  // per-edge 64x64 matrices (491MB)
__device__ float g_gi[NMAX * 192];           // GRU gates (input side)
__device__ float g_gh[NMAX * 192];           // GRU gates (hidden side)
__device__ int   g_deg[NMAX];
__device__ float g_invdeg[NMAX];
__device__ float g_wihT[DIM * 192];          // transposed GRU weights [64][192]
__device__ float g_whhT[DIM * 192];
__device__ float g_s2s_wihT[128 * 256];      // transposed LSTM weights [128][256]
__device__ float g_s2s_whhT[DIM * 256];      // [64][256]
__device__ float g_qstar[BMAX * 128];
__device__ float g_lh[BMAX * DIM];
__device__ float g_lc[BMAX * DIM];
__device__ float g_e[NMAX];
__device__ int   g_start[BMAX];
__device__ int   g_cnt[BMAX];
__device__ float g_y[BMAX * DIM];

__device__ __forceinline__ float sigf(float x) { return 1.f / (1.f + expf(-x)); }

// ---------------- small utility kernels --------------------------------------
__global__ void k_zero_f(float* p, int n) {
    int i = blockIdx.x * blockDim.x + threadIdx.x;
    if (i < n) p[i] = 0.f;
}
__global__ void k_zero_i(int* p, int n) {
    int i = blockIdx.x * blockDim.x + threadIdx.x;
    if (i < n) p[i] = 0;
}
// dst[k*G + g] = src[g*K + k]   (W [G,K] -> WT [K,G])
__global__ void k_transpose(float* dst, const float* __restrict__ src, int G, int K) {
    int idx = blockIdx.x * blockDim.x + threadIdx.x;
    if (idx >= G * K) return;
    int g = idx / K, k = idx % K;
    dst[k * G + g] = src[idx];
}

// ---------------- lin0: h = relu(nf @ W + b)  [N,30]@[30,64] ------------------
__global__ void k_lin0(const float* __restrict__ nf, const float* __restrict__ w,
                       const float* __restrict__ b, int N) {
    int idx = blockIdx.x * blockDim.x + threadIdx.x;
    if (idx >= N * DIM) return;
    int n = idx >> 6, d = idx & 63;
    float acc = b[d];
    #pragma unroll
    for (int k = 0; k < 30; k++) acc = fmaf(nf[n * 30 + k], w[k * DIM + d], acc);
    g_h[idx] = fmaxf(acc, 0.f);
}

// ---------------- ENN hidden: a = relu(ef @ W1 + b1)  [E,11]@[11,128] ---------
__global__ void k_enn1(const float* __restrict__ ef, const float* __restrict__ w1,
                       const float* __restrict__ b1, int E) {
    int idx = blockIdx.x * blockDim.x + threadIdx.x;
    if (idx >= E * 128) return;
    int e = idx >> 7, j = idx & 127;
    float acc = b1[j];
    #pragma unroll
    for (int k = 0; k < 11; k++) acc = fmaf(ef[e * 11 + k], w1[k * 128 + j], acc);
    g_ahid[idx] = fmaxf(acc, 0.f);
}

// ---------------- degrees ----------------------------------------------------
__global__ void k_count(const int* __restrict__ ei, int E) {
    int e = blockIdx.x * blockDim.x + threadIdx.x;
    if (e < E) atomicAdd(&g_deg[ei[E + e]], 1);
}
__global__ void k_invdeg(int N) {
    int n = blockIdx.x * blockDim.x + threadIdx.x;
    if (n < N) g_invdeg[n] = 1.f / fmaxf((float)g_deg[n], 1.f);
}

// ---------------- generic tiled SGEMM: C = A@B + bias[col] -------------------
// A [M,K] row-major, B [K,N] row-major, C [M,N]. BM=BN=128, BK=16, 256 thr.
__global__ void k_gemm(const float* __restrict__ A, const float* __restrict__ Bm,
                       const float* __restrict__ bias, float* __restrict__ C,
                       int M, int N, int K) {
    __shared__ float As[16][128];
    __shared__ float Bs[16][128];
    const int tid = threadIdx.x;
    const int bm = blockIdx.y * 128;
    const int bn = blockIdx.x * 128;
    const int tx = tid & 15, ty = tid >> 4;
    float acc[8][8];
    #pragma unroll
    for (int i = 0; i < 8; i++)
        #pragma unroll
        for (int j = 0; j < 8; j++) acc[i][j] = 0.f;

    for (int k0 = 0; k0 < K; k0 += 16) {
        #pragma unroll
        for (int l = 0; l < 2; l++) {
            int idx = tid + l * 256;     // 512 float4 units of the 128x16 A tile
            int r = idx >> 2;
            int kq = (idx & 3) << 2;
            float4 v = make_float4(0.f, 0.f, 0.f, 0.f);
            int grow = bm + r;
            if (grow < M) v = *reinterpret_cast<const float4*>(A + (size_t)grow * K + k0 + kq);
            As[kq + 0][r] = v.x; As[kq + 1][r] = v.y;
            As[kq + 2][r] = v.z; As[kq + 3][r] = v.w;
        }
        #pragma unroll
        for (int l = 0; l < 2; l++) {
            int idx = tid + l * 256;     // 512 float4 units of the 16x128 B tile
            int kr = idx >> 5;
            int c4 = (idx & 31) << 2;
            int gcol = bn + c4;
            float4 v = make_float4(0.f, 0.f, 0.f, 0.f);
            if (gcol < N) v = *reinterpret_cast<const float4*>(Bm + (size_t)(k0 + kr) * N + gcol);
            *reinterpret_cast<float4*>(&Bs[kr][c4]) = v;
        }
        __syncthreads();
        #pragma unroll
        for (int kk = 0; kk < 16; kk++) {
            float af[8], bf[8];
            *(float4*)&af[0] = *(const float4*)&As[kk][ty * 8];
            *(float4*)&af[4] = *(const float4*)&As[kk][ty * 8 + 4];
            *(float4*)&bf[0] = *(const float4*)&Bs[kk][tx * 8];
            *(float4*)&bf[4] = *(const float4*)&Bs[kk][tx * 8 + 4];
            #pragma unroll
            for (int i = 0; i < 8; i++)
                #pragma unroll
                for (int j = 0; j < 8; j++) acc[i][j] = fmaf(af[i], bf[j], acc[i][j]);
        }
        __syncthreads();
    }
    #pragma unroll
    for (int i = 0; i < 8; i++) {
        int grow = bm + ty * 8 + i;
        if (grow >= M) continue;
        #pragma unroll
        for (int j = 0; j < 8; j++) {
            int gcol = bn + tx * 8 + j;
            if (gcol < N) C[(size_t)grow * N + gcol] = acc[i][j] + bias[gcol];
        }
    }
}

// ---------------- per-edge message: msg[e]=feat[src[e]]@ew[e]; atomic agg ----
// 256 threads = 4 edges x 64 output dims
__global__ void k_msg(const int* __restrict__ ei, int E) {
    __shared__ float f_sh[4][DIM];
    int t = threadIdx.x;
    int eg = t >> 6, o = t & 63;
    int e = blockIdx.x * 4 + eg;
    if (e < E) {
        int src = ei[e];
        f_sh[eg][o] = g_h[(size_t)src * DIM + o];
    }
    __syncthreads();
    if (e >= E) return;
    const float* ew = &g_ew[(size_t)e * 4096 + o];
    const float* f = f_sh[eg];
    float acc = 0.f;
    #pragma unroll
    for (int i = 0; i < DIM; i++) acc = fmaf(f[i], ew[(size_t)i * DIM], acc);
    int dst = ei[E + e];
    atomicAdd(&g_agg[(size_t)dst * DIM + o], acc);
}

// ---------------- m = relu(agg*inv_deg + conv_b) -----------------------------
__global__ void k_mrelu(const float* __restrict__ conv_b, int N) {
    int idx = blockIdx.x * blockDim.x + threadIdx.x;
    if (idx >= N * DIM) return;
    int n = idx >> 6, d = idx & 63;
    g_m[idx] = fmaxf(fmaf(g_agg[idx], g_invdeg[n], conv_b[d]), 0.f);
}

// ---------------- GRU combine (gates already in g_gi/g_gh) -------------------
__global__ void k_gru_combine(int N) {
    int idx = blockIdx.x * blockDim.x + threadIdx.x;
    if (idx >= N * DIM) return;
    int n = idx >> 6, d = idx & 63;
    const float* gi = &g_gi[(size_t)n * 192];
    const float* gh = &g_gh[(size_t)n * 192];
    float r = sigf(gi[d] + gh[d]);
    float z = sigf(gi[64 + d] + gh[64 + d]);
    float nn = tanhf(fmaf(r, gh[128 + d], gi[128 + d]));
    float hold = g_h[idx];
    g_h[idx] = fmaf(z, hold - nn, nn);   // (1-z)*nn + z*h
}

// ---------------- graph segment offsets (graph_index is sorted) --------------
__global__ void k_seg_zero(int B, int N) {
    int b = threadIdx.x;
    if (b < B) { g_start[b] = 0x7fffffff; g_cnt[b] = 0; }
}
__global__ void k_seg_scan(const int* __restrict__ gidx, int N) {
    int n = blockIdx.x * blockDim.x + threadIdx.x;
    if (n >= N) return;
    int g = gidx[n];
    atomicMin(&g_start[g], n);
    atomicAdd(&g_cnt[g], 1);
}
__global__ void k_s2s_init(int B) {
    int i = blockIdx.x * blockDim.x + threadIdx.x;
    if (i < B * 128) g_qstar[i] = 0.f;
    if (i < B * DIM) { g_lh[i] = 0.f; g_lc[i] = 0.f; }
}

// ---------------- Set2Set LSTM step: one block per graph ---------------------
__global__ void k_lstm(const float* __restrict__ bih, const float* __restrict__ bhh) {
    int b = blockIdx.x;
    int g = threadIdx.x;           // 256 gates
    __shared__ float q_sh[128];
    __shared__ float h_sh[DIM];
    __shared__ float gates[256];
    if (g < 128) q_sh[g] = g_qstar[b * 128 + g];
    if (g < DIM) h_sh[g] = g_lh[b * DIM + g];
    __syncthreads();
    float acc = bih[g] + bhh[g];
    #pragma unroll 8
    for (int k = 0; k < 128; k++) acc = fmaf(q_sh[k], g_s2s_wihT[k * 256 + g], acc);
    #pragma unroll 8
    for (int k = 0; k < DIM; k++) acc = fmaf(h_sh[k], g_s2s_whhT[k * 256 + g], acc);
    gates[g] = acc;
    __syncthreads();
    if (g < DIM) {
        float i_g = sigf(gates[g]);
        float f_g = sigf(gates[64 + g]);
        float gg  = tanhf(gates[128 + g]);
        float o_g = sigf(gates[192 + g]);
        float c = fmaf(f_g, g_lc[b * DIM + g], i_g * gg);
        g_lc[b * DIM + g] = c;
        g_lh[b * DIM + g] = o_g * tanhf(c);
    }
}

// ---------------- Set2Set attention + readout: one block per graph -----------
__global__ void k_attn(int B) {
    int b = blockIdx.x;
    int t = threadIdx.x;           // 256 threads
    __shared__ float lh_sh[DIM];
    __shared__ float red[256];
    __shared__ float rpart[4][DIM];
    int s = g_start[b], c = g_cnt[b];
    if (t < DIM) lh_sh[t] = g_lh[b * DIM + t];
    __syncthreads();

    // phase 1: e_n = <feat_n, lh>, block max
    float lmax = -CUDART_INF_F;
    for (int n = s + t; n < s + c; n += 256) {
        const float* hp = &g_h[(size_t)n * DIM];
        float d = 0.f;
        #pragma unroll 8
        for (int k = 0; k < DIM; k++) d = fmaf(hp[k], lh_sh[k], d);
        g_e[n] = d;
        lmax = fmaxf(lmax, d);
    }
    red[t] = lmax;
    __syncthreads();
    for (int off = 128; off > 0; off >>= 1) {
        if (t < off) red[t] = fmaxf(red[t], red[t + off]);
        __syncthreads();
    }
    float emax = red[0];
    __syncthreads();

    // phase 2: sum of exp
    float lsum = 0.f;
    for (int n = s + t; n < s + c; n += 256) lsum += expf(g_e[n] - emax);
    red[t] = lsum;
    __syncthreads();
    for (int off = 128; off > 0; off >>= 1) {
        if (t < off) red[t] += red[t + off];
        __syncthreads();
    }
    float asum = red[0];
    float inv = asum > 0.f ? 1.f / asum : 0.f;
    __syncthreads();

    // phase 3: r = sum_n a_n * feat_n
    int d = t & 63, sub = t >> 6;
    float acc = 0.f;
    for (int n = s + sub; n < s + c; n += 4)
        acc = fmaf(expf(g_e[n] - emax), g_h[(size_t)n * DIM + d], acc);
    rpart[sub][d] = acc;
    __syncthreads();
    if (t < DIM) {
        float r = (rpart[0][t] + rpart[1][t] + rpart[2][t] + rpart[3][t]) * inv;
        g_qstar[b * 128 + 64 + t] = r;
        g_qstar[b * 128 + t] = g_lh[b * DIM + t];
    }
}

// ---------------- FC head ----------------------------------------------------
__global__ void k_fc1(const float* __restrict__ w, const float* __restrict__ bias) {
    int b = blockIdx.x;
    int t = threadIdx.x;           // 64
    __shared__ float q_sh[128];
    q_sh[t] = g_qstar[b * 128 + t];
    q_sh[t + 64] = g_qstar[b * 128 + t + 64];
    __syncthreads();
    float acc = bias[t];
    #pragma unroll 8
    for (int k = 0; k < 128; k++) acc = fmaf(q_sh[k], w[k * DIM + t], acc);
    g_y[b * DIM + t] = fmaxf(acc, 0.f);
}
__global__ void k_fc2(const float* __restrict__ w, const float* __restrict__ bias,
                      float* __restrict__ out, int B) {
    int b = blockIdx.x * blockDim.x + threadIdx.x;
    if (b >= B) return;
    float acc = bias[0];
    #pragma unroll 8
    for (int k = 0; k < DIM; k++) acc = fmaf(g_y[b * DIM + k], w[k], acc);
    out[b] = acc;
}

// ---------------- launch -----------------------------------------------------
extern "C" void kernel_launch(void* const* d_in, const int* in_sizes, int n_in,
                              void* d_out, int out_size) {
    const int N = in_sizes[0] / 30;
    const int E = in_sizes[1] / 11;
    const int B = out_size;

    const float* nf   = (const float*)d_in[0];
    const float* ef   = (const float*)d_in[1];
    const int*   ei   = (const int*)d_in[2];
    const int*   gidx = (const int*)d_in[3];
    // num_graphs may or may not be materialized as a size-1 input at index 4
    int wb = (in_sizes[4] == 1) ? 5 : 4;
    const float* lin0_w  = (const float*)d_in[wb + 0];
    const float* lin0_b  = (const float*)d_in[wb + 1];
    const float* enn_w1  = (const float*)d_in[wb + 2];
    const float* enn_b1  = (const float*)d_in[wb + 3];
    const float* enn_w2  = (const float*)d_in[wb + 4];
    const float* enn_b2  = (const float*)d_in[wb + 5];
    const float* conv_b  = (const float*)d_in[wb + 6];
    const float* gru_wih = (const float*)d_in[wb + 7];
    const float* gru_whh = (const float*)d_in[wb + 8];
    const float* gru_bih = (const float*)d_in[wb + 9];
    const float* gru_bhh = (const float*)d_in[wb + 10];
    const float* s2s_wih = (const float*)d_in[wb + 11];
    const float* s2s_whh = (const float*)d_in[wb + 12];
    const float* s2s_bih = (const float*)d_in[wb + 13];
    const float* s2s_bhh = (const float*)d_in[wb + 14];
    const float* fc1_w   = (const float*)d_in[wb + 15];
    const float* fc1_b   = (const float*)d_in[wb + 16];
    const float* fc2_w   = (const float*)d_in[wb + 17];
    const float* fc2_b   = (const float*)d_in[wb + 18];
    float* out = (float*)d_out;

    float *p_wihT, *p_whhT, *p_swihT, *p_swhhT, *p_ahid, *p_ew, *p_h, *p_m, *p_gi, *p_gh, *p_agg;
    cudaGetSymbolAddress((void**)&p_wihT, g_wihT);
    cudaGetSymbolAddress((void**)&p_whhT, g_whhT);
    cudaGetSymbolAddress((void**)&p_swihT, g_s2s_wihT);
    cudaGetSymbolAddress((void**)&p_swhhT, g_s2s_whhT);
    cudaGetSymbolAddress((void**)&p_ahid, g_ahid);
    cudaGetSymbolAddress((void**)&p_ew, g_ew);
    cudaGetSymbolAddress((void**)&p_h, g_h);
    cudaGetSymbolAddress((void**)&p_m, g_m);
    cudaGetSymbolAddress((void**)&p_gi, g_gi);
    cudaGetSymbolAddress((void**)&p_gh, g_gh);
    cudaGetSymbolAddress((void**)&p_agg, g_agg);

    // weight transposes (tiny)
    k_transpose<<<(192 * 64 + 255) / 256, 256>>>(p_wihT, gru_wih, 192, 64);
    k_transpose<<<(192 * 64 + 255) / 256, 256>>>(p_whhT, gru_whh, 192, 64);
    k_transpose<<<(256 * 128 + 255) / 256, 256>>>(p_swihT, s2s_wih, 256, 128);
    k_transpose<<<(256 * 64 + 255) / 256, 256>>>(p_swhhT, s2s_whh, 256, 64);

    // lin0 + degrees + ENN
    k_lin0<<<(N * DIM + 255) / 256, 256>>>(nf, lin0_w, lin0_b, N);
    {
        int* p_deg; cudaGetSymbolAddress((void**)&p_deg, g_deg);
        k_zero_i<<<(N + 255) / 256, 256>>>(p_deg, N);
    }
    k_count<<<(E + 255) / 256, 256>>>(ei, E);
    k_invdeg<<<(N + 255) / 256, 256>>>(N);
    k_enn1<<<(E * 128 + 255) / 256, 256>>>(ef, enn_w1, enn_b1, E);

    // big GEMM: ew = ahid @ W2 + b2   [E,128]@[128,4096]
    {
        dim3 grid(4096 / 128, (E + 127) / 128);
        k_gemm<<<grid, 256>>>(p_ahid, enn_w2, enn_b2, p_ew, E, 4096, 128);
    }

    // 3 message-passing + GRU iterations
    for (int it = 0; it < 3; it++) {
        k_zero_f<<<(N * DIM + 255) / 256, 256>>>(p_agg, N * DIM);
        k_msg<<<(E + 3) / 4, 256>>>(ei, E);
        k_mrelu<<<(N * DIM + 255) / 256, 256>>>(conv_b, N);
        {
            dim3 grid((192 + 127) / 128, (N + 127) / 128);
            k_gemm<<<grid, 256>>>(p_m, p_wihT, gru_bih, p_gi, N, 192, 64);
            k_gemm<<<grid, 256>>>(p_h, p_whhT, gru_bhh, p_gh, N, 192, 64);
        }
        k_gru_combine<<<(N * DIM + 255) / 256, 256>>>(N);
    }

    // Set2Set
    k_seg_zero<<<1, 128>>>(B, N);
    k_seg_scan<<<(N + 255) / 256, 256>>>(gidx, N);
    k_s2s_init<<<(B * 128 + 255) / 256, 256>>>(B);
    for (int it = 0; it < 3; it++) {
        k_lstm<<<B, 256>>>(s2s_bih, s2s_bhh);
        k_attn<<<B, 256>>>(B);
    }

    // FC head
    k_fc1<<<B, 64>>>(fc1_w, fc1_b);
    k_fc2<<<(B + 127) / 128, 128>>>(fc2_w, fc2_b, out, B);
}

// round 2
// speedup vs baseline: 1.0938x; 1.0938x over previous
#include <cuda_runtime.h>
#include <cstdint>
#include <math_constants.h>

// ---------------- problem-size capacities (fixed by the dataset) -------------
#define NMAX 20000
#define EMAX 30000
#define BMAX 128
#define DIM  64

// ---------------- device scratch (static: no allocations allowed) ------------
__device__ float g_h[NMAX * DIM];            // node hidden state (== feat)
__device__ float g_agg[NMAX * DIM];          // message aggregate
__device__ float g_m[NMAX * DIM];            // GRU input m
__device__ float g_ahid[EMAX * 128];         // ENN hidden
__device__ float g_ew[(size_t)EMAX * 4096];  // per-edge 64x64 matrices (491MB)
__device__ float g_gi[NMAX * 192];           // GRU gates (input side)
__device__ float g_gh[NMAX * 192];           // GRU gates (hidden side)
__device__ int   g_deg[NMAX];
__device__ float g_invdeg[NMAX];
__device__ float g_wihT[DIM * 192];          // transposed GRU weights [64][192]
__device__ float g_whhT[DIM * 192];
__device__ float g_s2s_wihT[128 * 256];      // transposed LSTM weights [128][256]
__device__ float g_s2s_whhT[DIM * 256];      // [64][256]
__device__ float g_qstar[BMAX * 128];
__device__ float g_lh[BMAX * DIM];
__device__ float g_lc[BMAX * DIM];
__device__ float g_e[NMAX];
__device__ int   g_start[BMAX];
__device__ int   g_cnt[BMAX];
__device__ float g_y[BMAX * DIM];

__device__ __forceinline__ float sigf(float x) { return 1.f / (1.f + expf(-x)); }

__device__ __forceinline__ unsigned f2tf32(float f) {
    unsigned u;
    asm volatile("cvt.rna.tf32.f32 %0, %1;" : "=r"(u) : "f"(f));
    return u;
}

// ---------------- small utility kernels --------------------------------------
__global__ void k_zero_f(float* p, int n) {
    int i = blockIdx.x * blockDim.x + threadIdx.x;
    if (i < n) p[i] = 0.f;
}
__global__ void k_zero_i(int* p, int n) {
    int i = blockIdx.x * blockDim.x + threadIdx.x;
    if (i < n) p[i] = 0;
}
// dst[k*G + g] = src[g*K + k]   (W [G,K] -> WT [K,G])
__global__ void k_transpose(float* dst, const float* __restrict__ src, int G, int K) {
    int idx = blockIdx.x * blockDim.x + threadIdx.x;
    if (idx >= G * K) return;
    int g = idx / K, k = idx % K;
    dst[k * G + g] = src[idx];
}

// ---------------- lin0: h = relu(nf @ W + b)  [N,30]@[30,64] ------------------
__global__ void k_lin0(const float* __restrict__ nf, const float* __restrict__ w,
                       const float* __restrict__ b, int N) {
    int idx = blockIdx.x * blockDim.x + threadIdx.x;
    if (idx >= N * DIM) return;
    int n = idx >> 6, d = idx & 63;
    float acc = b[d];
    #pragma unroll
    for (int k = 0; k < 30; k++) acc = fmaf(nf[n * 30 + k], w[k * DIM + d], acc);
    g_h[idx] = fmaxf(acc, 0.f);
}

// ---------------- ENN hidden: a = relu(ef @ W1 + b1)  [E,11]@[11,128] ---------
__global__ void k_enn1(const float* __restrict__ ef, const float* __restrict__ w1,
                       const float* __restrict__ b1, int E) {
    int idx = blockIdx.x * blockDim.x + threadIdx.x;
    if (idx >= E * 128) return;
    int e = idx >> 7, j = idx & 127;
    float acc = b1[j];
    #pragma unroll
    for (int k = 0; k < 11; k++) acc = fmaf(ef[e * 11 + k], w1[k * 128 + j], acc);
    g_ahid[idx] = fmaxf(acc, 0.f);
}

// ---------------- degrees ----------------------------------------------------
__global__ void k_count(const int* __restrict__ ei, int E) {
    int e = blockIdx.x * blockDim.x + threadIdx.x;
    if (e < E) atomicAdd(&g_deg[ei[E + e]], 1);
}
__global__ void k_invdeg(int N) {
    int n = blockIdx.x * blockDim.x + threadIdx.x;
    if (n < N) g_invdeg[n] = 1.f / fmaxf((float)g_deg[n], 1.f);
}

// ---------------- tf32 tensor-core GEMM: C = A@B + bias ----------------------
// Specialized: A [M,128] row-major, B [128,4096] row-major, C [M,4096].
// Block tile 128x128, BK=32, 256 threads = 8 warps (2x4), warp tile 64x32.
// Fragments are pre-swizzled into smem in mma.m16n8k8 register layout.
__global__ void k_gemm_tf32(const float* __restrict__ A, const float* __restrict__ Bm,
                            const float* __restrict__ bias, float* __restrict__ C,
                            int M) {
    __shared__ __align__(16) unsigned Af[8][4][32][4];  // [mt][kt][lane][slot]
    __shared__ __align__(16) unsigned Bf[4][16][32][2]; // [kt][nt][lane][slot]
    const int tid = threadIdx.x;
    const int lane = tid & 31, warp = tid >> 5;
    const int wm = warp >> 2, wn = warp & 3;
    const int bm = blockIdx.y << 7, bn = blockIdx.x << 7;

    float acc[4][4][4];
    #pragma unroll
    for (int i = 0; i < 4; i++)
        #pragma unroll
        for (int j = 0; j < 4; j++)
            #pragma unroll
            for (int c = 0; c < 4; c++) acc[i][j][c] = 0.f;

    for (int k0 = 0; k0 < 128; k0 += 32) {
        // A tile 128x32 -> fragment layout
        #pragma unroll
        for (int l = 0; l < 4; l++) {
            int idx = tid + (l << 8);
            int r = idx >> 3, kq = (idx & 7) << 2;
            float4 v = make_float4(0.f, 0.f, 0.f, 0.f);
            if (bm + r < M) v = *reinterpret_cast<const float4*>(A + (size_t)(bm + r) * 128 + k0 + kq);
            int mt = r >> 4, r16 = r & 15;
            float vv[4] = {v.x, v.y, v.z, v.w};
            #pragma unroll
            for (int j = 0; j < 4; j++) {
                int k = kq + j, kt = k >> 3, k8 = k & 7;
                int slot = (r16 >> 3) + ((k8 >> 2) << 1);
                int ln = ((r16 & 7) << 2) + (k8 & 3);
                Af[mt][kt][ln][slot] = f2tf32(vv[j]);
            }
        }
        // B tile 32x128 -> fragment layout
        #pragma unroll
        for (int l = 0; l < 4; l++) {
            int idx = tid + (l << 8);
            int kr = idx >> 5, c4 = (idx & 31) << 2;
            float4 v = *reinterpret_cast<const float4*>(Bm + (size_t)(k0 + kr) * 4096 + bn + c4);
            int kt = kr >> 3, k8 = kr & 7;
            float vv[4] = {v.x, v.y, v.z, v.w};
            #pragma unroll
            for (int j = 0; j < 4; j++) {
                int c = c4 + j, nt = c >> 3, c8 = c & 7;
                Bf[kt][nt][(c8 << 2) + (k8 & 3)][k8 >> 2] = f2tf32(vv[j]);
            }
        }
        __syncthreads();
        #pragma unroll
        for (int kt = 0; kt < 4; kt++) {
            unsigned a[4][4], b[4][2];
            #pragma unroll
            for (int i = 0; i < 4; i++)
                *reinterpret_cast<uint4*>(a[i]) = *reinterpret_cast<const uint4*>(&Af[(wm << 2) + i][kt][lane][0]);
            #pragma unroll
            for (int j = 0; j < 4; j++)
                *reinterpret_cast<uint2*>(b[j]) = *reinterpret_cast<const uint2*>(&Bf[kt][(wn << 2) + j][lane][0]);
            #pragma unroll
            for (int i = 0; i < 4; i++)
                #pragma unroll
                for (int j = 0; j < 4; j++)
                    asm volatile(
                        "mma.sync.aligned.m16n8k8.row.col.f32.tf32.tf32.f32 "
                        "{%0,%1,%2,%3}, {%4,%5,%6,%7}, {%8,%9}, {%0,%1,%2,%3};"
                        : "+f"(acc[i][j][0]), "+f"(acc[i][j][1]),
                          "+f"(acc[i][j][2]), "+f"(acc[i][j][3])
                        : "r"(a[i][0]), "r"(a[i][1]), "r"(a[i][2]), "r"(a[i][3]),
                          "r"(b[j][0]), "r"(b[j][1]));
        }
        __syncthreads();
    }
    // epilogue: add bias, store float2 pairs
    int g = lane >> 2, tg = lane & 3;
    #pragma unroll
    for (int i = 0; i < 4; i++) {
        int r0 = bm + (wm << 6) + (i << 4) + g;
        #pragma unroll
        for (int j = 0; j < 4; j++) {
            int col = bn + (wn << 5) + (j << 3) + (tg << 1);
            float b0 = bias[col], b1 = bias[col + 1];
            if (r0 < M)
                *reinterpret_cast<float2*>(C + (size_t)r0 * 4096 + col) =
                    make_float2(acc[i][j][0] + b0, acc[i][j][1] + b1);
            if (r0 + 8 < M)
                *reinterpret_cast<float2*>(C + (size_t)(r0 + 8) * 4096 + col) =
                    make_float2(acc[i][j][2] + b0, acc[i][j][3] + b1);
        }
    }
}

// ---------------- generic tiled SGEMM (used for small GRU GEMMs) -------------
__global__ void k_gemm(const float* __restrict__ A, const float* __restrict__ Bm,
                       const float* __restrict__ bias, float* __restrict__ C,
                       int M, int N, int K) {
    __shared__ float As[16][128];
    __shared__ float Bs[16][128];
    const int tid = threadIdx.x;
    const int bm = blockIdx.y * 128;
    const int bn = blockIdx.x * 128;
    const int tx = tid & 15, ty = tid >> 4;
    float acc[8][8];
    #pragma unroll
    for (int i = 0; i < 8; i++)
        #pragma unroll
        for (int j = 0; j < 8; j++) acc[i][j] = 0.f;

    for (int k0 = 0; k0 < K; k0 += 16) {
        #pragma unroll
        for (int l = 0; l < 2; l++) {
            int idx = tid + l * 256;
            int r = idx >> 2;
            int kq = (idx & 3) << 2;
            float4 v = make_float4(0.f, 0.f, 0.f, 0.f);
            int grow = bm + r;
            if (grow < M) v = *reinterpret_cast<const float4*>(A + (size_t)grow * K + k0 + kq);
            As[kq + 0][r] = v.x; As[kq + 1][r] = v.y;
            As[kq + 2][r] = v.z; As[kq + 3][r] = v.w;
        }
        #pragma unroll
        for (int l = 0; l < 2; l++) {
            int idx = tid + l * 256;
            int kr = idx >> 5;
            int c4 = (idx & 31) << 2;
            int gcol = bn + c4;
            float4 v = make_float4(0.f, 0.f, 0.f, 0.f);
            if (gcol < N) v = *reinterpret_cast<const float4*>(Bm + (size_t)(k0 + kr) * N + gcol);
            *reinterpret_cast<float4*>(&Bs[kr][c4]) = v;
        }
        __syncthreads();
        #pragma unroll
        for (int kk = 0; kk < 16; kk++) {
            float af[8], bf[8];
            *(float4*)&af[0] = *(const float4*)&As[kk][ty * 8];
            *(float4*)&af[4] = *(const float4*)&As[kk][ty * 8 + 4];
            *(float4*)&bf[0] = *(const float4*)&Bs[kk][tx * 8];
            *(float4*)&bf[4] = *(const float4*)&Bs[kk][tx * 8 + 4];
            #pragma unroll
            for (int i = 0; i < 8; i++)
                #pragma unroll
                for (int j = 0; j < 8; j++) acc[i][j] = fmaf(af[i], bf[j], acc[i][j]);
        }
        __syncthreads();
    }
    #pragma unroll
    for (int i = 0; i < 8; i++) {
        int grow = bm + ty * 8 + i;
        if (grow >= M) continue;
        #pragma unroll
        for (int j = 0; j < 8; j++) {
            int gcol = bn + tx * 8 + j;
            if (gcol < N) C[(size_t)grow * N + gcol] = acc[i][j] + bias[gcol];
        }
    }
}

// ---------------- per-edge message: msg[e]=feat[src[e]]@ew[e]; atomic agg ----
__global__ void k_msg(const int* __restrict__ ei, int E) {
    __shared__ float f_sh[4][DIM];
    int t = threadIdx.x;
    int eg = t >> 6, o = t & 63;
    int e = blockIdx.x * 4 + eg;
    if (e < E) {
        int src = ei[e];
        f_sh[eg][o] = g_h[(size_t)src * DIM + o];
    }
    __syncthreads();
    if (e >= E) return;
    const float* ew = &g_ew[(size_t)e * 4096 + o];
    const float* f = f_sh[eg];
    float acc = 0.f;
    #pragma unroll
    for (int i = 0; i < DIM; i++) acc = fmaf(f[i], ew[(size_t)i * DIM], acc);
    int dst = ei[E + e];
    atomicAdd(&g_agg[(size_t)dst * DIM + o], acc);
}

// ---------------- m = relu(agg*inv_deg + conv_b) -----------------------------
__global__ void k_mrelu(const float* __restrict__ conv_b, int N) {
    int idx = blockIdx.x * blockDim.x + threadIdx.x;
    if (idx >= N * DIM) return;
    int n = idx >> 6, d = idx & 63;
    g_m[idx] = fmaxf(fmaf(g_agg[idx], g_invdeg[n], conv_b[d]), 0.f);
}

// ---------------- GRU combine (gates already in g_gi/g_gh) -------------------
__global__ void k_gru_combine(int N) {
    int idx = blockIdx.x * blockDim.x + threadIdx.x;
    if (idx >= N * DIM) return;
    int n = idx >> 6, d = idx & 63;
    const float* gi = &g_gi[(size_t)n * 192];
    const float* gh = &g_gh[(size_t)n * 192];
    float r = sigf(gi[d] + gh[d]);
    float z = sigf(gi[64 + d] + gh[64 + d]);
    float nn = tanhf(fmaf(r, gh[128 + d], gi[128 + d]));
    float hold = g_h[idx];
    g_h[idx] = fmaf(z, hold - nn, nn);
}

// ---------------- graph segment offsets (graph_index is sorted) --------------
__global__ void k_seg_zero(int B, int N) {
    int b = threadIdx.x;
    if (b < B) { g_start[b] = 0x7fffffff; g_cnt[b] = 0; }
}
__global__ void k_seg_scan(const int* __restrict__ gidx, int N) {
    int n = blockIdx.x * blockDim.x + threadIdx.x;
    if (n >= N) return;
    int g = gidx[n];
    atomicMin(&g_start[g], n);
    atomicAdd(&g_cnt[g], 1);
}
__global__ void k_s2s_init(int B) {
    int i = blockIdx.x * blockDim.x + threadIdx.x;
    if (i < B * 128) g_qstar[i] = 0.f;
    if (i < B * DIM) { g_lh[i] = 0.f; g_lc[i] = 0.f; }
}

// ---------------- Set2Set LSTM step: one block per graph ---------------------
__global__ void k_lstm(const float* __restrict__ bih, const float* __restrict__ bhh) {
    int b = blockIdx.x;
    int g = threadIdx.x;           // 256 gates
    __shared__ float q_sh[128];
    __shared__ float h_sh[DIM];
    __shared__ float gates[256];
    if (g < 128) q_sh[g] = g_qstar[b * 128 + g];
    if (g < DIM) h_sh[g] = g_lh[b * DIM + g];
    __syncthreads();
    float acc = bih[g] + bhh[g];
    #pragma unroll 8
    for (int k = 0; k < 128; k++) acc = fmaf(q_sh[k], g_s2s_wihT[k * 256 + g], acc);
    #pragma unroll 8
    for (int k = 0; k < DIM; k++) acc = fmaf(h_sh[k], g_s2s_whhT[k * 256 + g], acc);
    gates[g] = acc;
    __syncthreads();
    if (g < DIM) {
        float i_g = sigf(gates[g]);
        float f_g = sigf(gates[64 + g]);
        float gg  = tanhf(gates[128 + g]);
        float o_g = sigf(gates[192 + g]);
        float c = fmaf(f_g, g_lc[b * DIM + g], i_g * gg);
        g_lc[b * DIM + g] = c;
        g_lh[b * DIM + g] = o_g * tanhf(c);
    }
}

// ---------------- Set2Set attention + readout: one block per graph -----------
__global__ void k_attn(int B) {
    int b = blockIdx.x;
    int t = threadIdx.x;           // 256 threads
    __shared__ float lh_sh[DIM];
    __shared__ float red[256];
    __shared__ float rpart[4][DIM];
    int s = g_start[b], c = g_cnt[b];
    if (t < DIM) lh_sh[t] = g_lh[b * DIM + t];
    __syncthreads();

    float lmax = -CUDART_INF_F;
    for (int n = s + t; n < s + c; n += 256) {
        const float* hp = &g_h[(size_t)n * DIM];
        float d = 0.f;
        #pragma unroll 8
        for (int k = 0; k < DIM; k++) d = fmaf(hp[k], lh_sh[k], d);
        g_e[n] = d;
        lmax = fmaxf(lmax, d);
    }
    red[t] = lmax;
    __syncthreads();
    for (int off = 128; off > 0; off >>= 1) {
        if (t < off) red[t] = fmaxf(red[t], red[t + off]);
        __syncthreads();
    }
    float emax = red[0];
    __syncthreads();

    float lsum = 0.f;
    for (int n = s + t; n < s + c; n += 256) lsum += expf(g_e[n] - emax);
    red[t] = lsum;
    __syncthreads();
    for (int off = 128; off > 0; off >>= 1) {
        if (t < off) red[t] += red[t + off];
        __syncthreads();
    }
    float asum = red[0];
    float inv = asum > 0.f ? 1.f / asum : 0.f;
    __syncthreads();

    int d = t & 63, sub = t >> 6;
    float acc = 0.f;
    for (int n = s + sub; n < s + c; n += 4)
        acc = fmaf(expf(g_e[n] - emax), g_h[(size_t)n * DIM + d], acc);
    rpart[sub][d] = acc;
    __syncthreads();
    if (t < DIM) {
        float r = (rpart[0][t] + rpart[1][t] + rpart[2][t] + rpart[3][t]) * inv;
        g_qstar[b * 128 + 64 + t] = r;
        g_qstar[b * 128 + t] = g_lh[b * DIM + t];
    }
}

// ---------------- FC head ----------------------------------------------------
__global__ void k_fc1(const float* __restrict__ w, const float* __restrict__ bias) {
    int b = blockIdx.x;
    int t = threadIdx.x;           // 64
    __shared__ float q_sh[128];
    q_sh[t] = g_qstar[b * 128 + t];
    q_sh[t + 64] = g_qstar[b * 128 + t + 64];
    __syncthreads();
    float acc = bias[t];
    #pragma unroll 8
    for (int k = 0; k < 128; k++) acc = fmaf(q_sh[k], w[k * DIM + t], acc);
    g_y[b * DIM + t] = fmaxf(acc, 0.f);
}
__global__ void k_fc2(const float* __restrict__ w, const float* __restrict__ bias,
                      float* __restrict__ out, int B) {
    int b = blockIdx.x * blockDim.x + threadIdx.x;
    if (b >= B) return;
    float acc = bias[0];
    #pragma unroll 8
    for (int k = 0; k < DIM; k++) acc = fmaf(g_y[b * DIM + k], w[k], acc);
    out[b] = acc;
}

// ---------------- launch -----------------------------------------------------
extern "C" void kernel_launch(void* const* d_in, const int* in_sizes, int n_in,
                              void* d_out, int out_size) {
    const int N = in_sizes[0] / 30;
    const int E = in_sizes[1] / 11;
    const int B = out_size;

    const float* nf   = (const float*)d_in[0];
    const float* ef   = (const float*)d_in[1];
    const int*   ei   = (const int*)d_in[2];
    const int*   gidx = (const int*)d_in[3];
    int wb = (in_sizes[4] == 1) ? 5 : 4;
    const float* lin0_w  = (const float*)d_in[wb + 0];
    const float* lin0_b  = (const float*)d_in[wb + 1];
    const float* enn_w1  = (const float*)d_in[wb + 2];
    const float* enn_b1  = (const float*)d_in[wb + 3];
    const float* enn_w2  = (const float*)d_in[wb + 4];
    const float* enn_b2  = (const float*)d_in[wb + 5];
    const float* conv_b  = (const float*)d_in[wb + 6];
    const float* gru_wih = (const float*)d_in[wb + 7];
    const float* gru_whh = (const float*)d_in[wb + 8];
    const float* gru_bih = (const float*)d_in[wb + 9];
    const float* gru_bhh = (const float*)d_in[wb + 10];
    const float* s2s_wih = (const float*)d_in[wb + 11];
    const float* s2s_whh = (const float*)d_in[wb + 12];
    const float* s2s_bih = (const float*)d_in[wb + 13];
    const float* s2s_bhh = (const float*)d_in[wb + 14];
    const float* fc1_w   = (const float*)d_in[wb + 15];
    const float* fc1_b   = (const float*)d_in[wb + 16];
    const float* fc2_w   = (const float*)d_in[wb + 17];
    const float* fc2_b   = (const float*)d_in[wb + 18];
    float* out = (float*)d_out;

    float *p_wihT, *p_whhT, *p_swihT, *p_swhhT, *p_ahid, *p_ew, *p_h, *p_m, *p_gi, *p_gh, *p_agg;
    cudaGetSymbolAddress((void**)&p_wihT, g_wihT);
    cudaGetSymbolAddress((void**)&p_whhT, g_whhT);
    cudaGetSymbolAddress((void**)&p_swihT, g_s2s_wihT);
    cudaGetSymbolAddress((void**)&p_swhhT, g_s2s_whhT);
    cudaGetSymbolAddress((void**)&p_ahid, g_ahid);
    cudaGetSymbolAddress((void**)&p_ew, g_ew);
    cudaGetSymbolAddress((void**)&p_h, g_h);
    cudaGetSymbolAddress((void**)&p_m, g_m);
    cudaGetSymbolAddress((void**)&p_gi, g_gi);
    cudaGetSymbolAddress((void**)&p_gh, g_gh);
    cudaGetSymbolAddress((void**)&p_agg, g_agg);
    int* p_deg; cudaGetSymbolAddress((void**)&p_deg, g_deg);

    // Launches 1-5: prerequisites for the big GEMM
    k_lin0<<<(N * DIM + 255) / 256, 256>>>(nf, lin0_w, lin0_b, N);
    k_enn1<<<(E * 128 + 255) / 256, 256>>>(ef, enn_w1, enn_b1, E);
    k_zero_i<<<(N + 255) / 256, 256>>>(p_deg, N);
    k_count<<<(E + 255) / 256, 256>>>(ei, E);
    k_invdeg<<<(N + 255) / 256, 256>>>(N);

    // Launch 6 (ncu -s 5 -c 1 profiles this one): tf32 tensor-core GEMM
    // ew = ahid @ W2 + b2   [E,128]@[128,4096]
    {
        dim3 grid(4096 / 128, (E + 127) / 128);
        k_gemm_tf32<<<grid, 256>>>(p_ahid, enn_w2, enn_b2, p_ew, E);
    }

    // weight transposes (tiny; only needed before the GRU/LSTM steps)
    k_transpose<<<(192 * 64 + 255) / 256, 256>>>(p_wihT, gru_wih, 192, 64);
    k_transpose<<<(192 * 64 + 255) / 256, 256>>>(p_whhT, gru_whh, 192, 64);
    k_transpose<<<(256 * 128 + 255) / 256, 256>>>(p_swihT, s2s_wih, 256, 128);
    k_transpose<<<(256 * 64 + 255) / 256, 256>>>(p_swhhT, s2s_whh, 256, 64);

    // 3 message-passing + GRU iterations
    for (int it = 0; it < 3; it++) {
        k_zero_f<<<(N * DIM + 255) / 256, 256>>>(p_agg, N * DIM);
        k_msg<<<(E + 3) / 4, 256>>>(ei, E);
        k_mrelu<<<(N * DIM + 255) / 256, 256>>>(conv_b, N);
        {
            dim3 grid((192 + 127) / 128, (N + 127) / 128);
            k_gemm<<<grid, 256>>>(p_m, p_wihT, gru_bih, p_gi, N, 192, 64);
            k_gemm<<<grid, 256>>>(p_h, p_whhT, gru_bhh, p_gh, N, 192, 64);
        }
        k_gru_combine<<<(N * DIM + 255) / 256, 256>>>(N);
    }

    // Set2Set
    k_seg_zero<<<1, 128>>>(B, N);
    k_seg_scan<<<(N + 255) / 256, 256>>>(gidx, N);
    k_s2s_init<<<(B * 128 + 255) / 256, 256>>>(B);
    for (int it = 0; it < 3; it++) {
        k_lstm<<<B, 256>>>(s2s_bih, s2s_bhh);
        k_attn<<<B, 256>>>(B);
    }

    // FC head
    k_fc1<<<B, 64>>>(fc1_w, fc1_b);
    k_fc2<<<(B + 127) / 128, 128>>>(fc2_w, fc2_b, out, B);
}

// round 3
// speedup vs baseline: 1.4187x; 1.2971x over previous
#include <cuda_runtime.h>
#include <cuda_bf16.h>
#include <cstdint>
#include <math_constants.h>

// ---------------- problem-size capacities (fixed by the dataset) -------------
#define NMAX 20000
#define EMAX 30000
#define BMAX 128
#define DIM  64

// ---------------- device scratch (static: no allocations allowed) ------------
__device__ float g_h[NMAX * DIM];            // node hidden state (== feat)
__device__ float g_agg[NMAX * DIM];          // message aggregate
__device__ float g_m[NMAX * DIM];            // GRU input m
__device__ __nv_bfloat16 g_a3[(size_t)(EMAX + 128) * 384];  // bf16x3 split ENN hidden [E,384]
__device__ __nv_bfloat16 g_b3[(size_t)384 * 4096];          // bf16x3 split W2 [384,4096]
__device__ float g_ew[(size_t)EMAX * 4096];  // per-edge 64x64 matrices (491MB)
__device__ float g_gi[NMAX * 192];           // GRU gates (input side)
__device__ float g_gh[NMAX * 192];           // GRU gates (hidden side)
__device__ int   g_deg[NMAX];
__device__ float g_invdeg[NMAX];
__device__ float g_wihT[DIM * 192];          // transposed GRU weights [64][192]
__device__ float g_whhT[DIM * 192];
__device__ float g_s2s_wihT[128 * 256];      // transposed LSTM weights [128][256]
__device__ float g_s2s_whhT[DIM * 256];      // [64][256]
__device__ float g_qstar[BMAX * 128];
__device__ float g_lh[BMAX * DIM];
__device__ float g_lc[BMAX * DIM];
__device__ float g_e[NMAX];
__device__ int   g_start[BMAX];
__device__ int   g_cnt[BMAX];
__device__ float g_y[BMAX * DIM];

__device__ __forceinline__ float sigf(float x) { return 1.f / (1.f + expf(-x)); }

// ---------------- small utility kernels --------------------------------------
__global__ void k_zero_f(float* p, int n) {
    int i = blockIdx.x * blockDim.x + threadIdx.x;
    if (i < n) p[i] = 0.f;
}
__global__ void k_zero_i(int* p, int n) {
    int i = blockIdx.x * blockDim.x + threadIdx.x;
    if (i < n) p[i] = 0;
}
__global__ void k_transpose(float* dst, const float* __restrict__ src, int G, int K) {
    int idx = blockIdx.x * blockDim.x + threadIdx.x;
    if (idx >= G * K) return;
    int g = idx / K, k = idx % K;
    dst[k * G + g] = src[idx];
}

// ---------------- lin0: h = relu(nf @ W + b)  [N,30]@[30,64] ------------------
__global__ void k_lin0(const float* __restrict__ nf, const float* __restrict__ w,
                       const float* __restrict__ b, int N) {
    int idx = blockIdx.x * blockDim.x + threadIdx.x;
    if (idx >= N * DIM) return;
    int n = idx >> 6, d = idx & 63;
    float acc = b[d];
    #pragma unroll
    for (int k = 0; k < 30; k++) acc = fmaf(nf[n * 30 + k], w[k * DIM + d], acc);
    g_h[idx] = fmaxf(acc, 0.f);
}

// ---------------- ENN hidden with bf16x3 split: a=relu(ef@W1+b1), A*=[a0|a0|a1]
__global__ void k_enn1(const float* __restrict__ ef, const float* __restrict__ w1,
                       const float* __restrict__ b1, int E) {
    int idx = blockIdx.x * blockDim.x + threadIdx.x;
    if (idx >= E * 128) return;
    int e = idx >> 7, j = idx & 127;
    float acc = b1[j];
    #pragma unroll
    for (int k = 0; k < 11; k++) acc = fmaf(ef[e * 11 + k], w1[k * 128 + j], acc);
    acc = fmaxf(acc, 0.f);
    __nv_bfloat16 a0 = __float2bfloat16(acc);
    __nv_bfloat16 a1 = __float2bfloat16(acc - __bfloat162float(a0));
    size_t base = (size_t)e * 384;
    g_a3[base + j] = a0;
    g_a3[base + 128 + j] = a0;
    g_a3[base + 256 + j] = a1;
}

// ---------------- B* prep: [b0; b1; b0] from W2 [128,4096] -------------------
__global__ void k_prep_b(const float* __restrict__ w2) {
    int idx = blockIdx.x * blockDim.x + threadIdx.x;
    if (idx >= 128 * 4096) return;
    float w = w2[idx];
    __nv_bfloat16 b0 = __float2bfloat16(w);
    __nv_bfloat16 b1 = __float2bfloat16(w - __bfloat162float(b0));
    int row = idx >> 12, col = idx & 4095;
    g_b3[(size_t)row * 4096 + col] = b0;
    g_b3[(size_t)(128 + row) * 4096 + col] = b1;
    g_b3[(size_t)(256 + row) * 4096 + col] = b0;
}

// ---------------- degrees ----------------------------------------------------
__global__ void k_count(const int* __restrict__ ei, int E) {
    int e = blockIdx.x * blockDim.x + threadIdx.x;
    if (e < E) atomicAdd(&g_deg[ei[E + e]], 1);
}
__global__ void k_invdeg(int N) {
    int n = blockIdx.x * blockDim.x + threadIdx.x;
    if (n < N) g_invdeg[n] = 1.f / fmaxf((float)g_deg[n], 1.f);
}

// ---------------- bf16 tensor-core GEMM: C = A@B + bias ----------------------
// A [M,384] bf16 row-major (bf16x3-split), B [384,4096] bf16 row-major,
// C [M,4096] fp32. Block 128x128, BK=32, 256 thr = 8 warps (2x4), warp 64x32.
// Fragments pre-packed in smem in mma.m16n8k16 register layout; register-staged
// double buffering, one __syncthreads per stage.
__global__ void __launch_bounds__(256) k_gemm_bf16(
        const __nv_bfloat16* __restrict__ A, const __nv_bfloat16* __restrict__ Bm,
        const float* __restrict__ bias, float* __restrict__ C, int M) {
    __shared__ __align__(16) unsigned Af[2][8][2][33][4];  // [buf][mt][kt][lane(+pad)][reg]
    __shared__ __align__(16) unsigned Bf[2][2][16][33][2]; // [buf][kt][nt][lane(+pad)][reg]
    const int tid = threadIdx.x;
    const int lane = tid & 31, warp = tid >> 5;
    const int wm = warp >> 2, wn = warp & 3;
    const int bm = blockIdx.y << 7, bn = blockIdx.x << 7;

    float acc[4][4][4];
    #pragma unroll
    for (int i = 0; i < 4; i++)
        #pragma unroll
        for (int j = 0; j < 4; j++)
            #pragma unroll
            for (int c = 0; c < 4; c++) acc[i][j][c] = 0.f;

    uint4 ra[2];
    uint2 rb[2][2];

    // ---- staged gmem loads for stage s (k0 = 32*s) ----
    auto LDG = [&](int s) {
        int k0 = s << 5;
        #pragma unroll
        for (int l = 0; l < 2; l++) {
            int idx = tid + (l << 8);
            int r = idx >> 2, kq = (idx & 3) << 3;      // row 0..127, k offset {0,8,16,24}
            if (bm + r < M)
                ra[l] = *reinterpret_cast<const uint4*>(A + (size_t)(bm + r) * 384 + k0 + kq);
            else
                ra[l] = make_uint4(0u, 0u, 0u, 0u);
            int kp = idx >> 5, c4 = (idx & 31) << 2;    // k-pair 0..15, col group
            const __nv_bfloat16* p = Bm + (size_t)(k0 + 2 * kp) * 4096 + bn + c4;
            rb[l][0] = *reinterpret_cast<const uint2*>(p);
            rb[l][1] = *reinterpret_cast<const uint2*>(p + 4096);
        }
    };
    // ---- store staged regs into fragment-layout smem buffer ----
    auto STS = [&](int buf) {
        #pragma unroll
        for (int l = 0; l < 2; l++) {
            {   // A: uint4 = 8 bf16 along k = 4 packed pairs -> 4 lanes, same reg
                int idx = tid + (l << 8);
                int r = idx >> 2, kq = (idx & 3) << 3;
                int mt = r >> 4, r16 = r & 15;
                int kt = kq >> 4;
                int reg = (r16 >> 3) + (((kq >> 3) & 1) << 1);
                int ln0 = (r16 & 7) << 2;
                unsigned* dst = &Af[buf][mt][kt][0][0];
                dst[(ln0 + 0) * 4 + reg] = ra[l].x;
                dst[(ln0 + 1) * 4 + reg] = ra[l].y;
                dst[(ln0 + 2) * 4 + reg] = ra[l].z;
                dst[(ln0 + 3) * 4 + reg] = ra[l].w;
            }
            {   // B: pack (k,k+1) pairs per column
                int idx = tid + (l << 8);
                int kp = idx >> 5, c4 = (idx & 31) << 2;
                int ktb = kp >> 3, t = kp & 3, regb = (kp >> 2) & 1;
                unsigned u[4];
                u[0] = (rb[l][0].x & 0xFFFFu) | (rb[l][1].x << 16);
                u[1] = (rb[l][0].x >> 16) | (rb[l][1].x & 0xFFFF0000u);
                u[2] = (rb[l][0].y & 0xFFFFu) | (rb[l][1].y << 16);
                u[3] = (rb[l][0].y >> 16) | (rb[l][1].y & 0xFFFF0000u);
                #pragma unroll
                for (int j = 0; j < 4; j++) {
                    int n = c4 + j;
                    Bf[buf][ktb][n >> 3][((n & 7) << 2) + t][regb] = u[j];
                }
            }
        }
    };
    auto COMPUTE = [&](int buf) {
        #pragma unroll
        for (int kt = 0; kt < 2; kt++) {
            unsigned a[4][4], b[4][2];
            #pragma unroll
            for (int i = 0; i < 4; i++)
                *reinterpret_cast<uint4*>(a[i]) =
                    *reinterpret_cast<const uint4*>(&Af[buf][(wm << 2) + i][kt][lane][0]);
            #pragma unroll
            for (int j = 0; j < 4; j++)
                *reinterpret_cast<uint2*>(b[j]) =
                    *reinterpret_cast<const uint2*>(&Bf[buf][kt][(wn << 2) + j][lane][0]);
            #pragma unroll
            for (int i = 0; i < 4; i++)
                #pragma unroll
                for (int j = 0; j < 4; j++)
                    asm volatile(
                        "mma.sync.aligned.m16n8k16.row.col.f32.bf16.bf16.f32 "
                        "{%0,%1,%2,%3}, {%4,%5,%6,%7}, {%8,%9}, {%0,%1,%2,%3};"
                        : "+f"(acc[i][j][0]), "+f"(acc[i][j][1]),
                          "+f"(acc[i][j][2]), "+f"(acc[i][j][3])
                        : "r"(a[i][0]), "r"(a[i][1]), "r"(a[i][2]), "r"(a[i][3]),
                          "r"(b[j][0]), "r"(b[j][1]));
        }
    };

    LDG(0);
    STS(0);
    __syncthreads();
    #pragma unroll 1
    for (int s = 0; s < 12; s++) {
        if (s < 11) LDG(s + 1);
        COMPUTE(s & 1);
        if (s < 11) {
            STS((s + 1) & 1);
            __syncthreads();
        }
    }

    // epilogue: add bias, store float2 pairs
    int g = lane >> 2, tg = lane & 3;
    #pragma unroll
    for (int i = 0; i < 4; i++) {
        int r0 = bm + (wm << 6) + (i << 4) + g;
        #pragma unroll
        for (int j = 0; j < 4; j++) {
            int col = bn + (wn << 5) + (j << 3) + (tg << 1);
            float b0 = bias[col], b1 = bias[col + 1];
            if (r0 < M)
                *reinterpret_cast<float2*>(C + (size_t)r0 * 4096 + col) =
                    make_float2(acc[i][j][0] + b0, acc[i][j][1] + b1);
            if (r0 + 8 < M)
                *reinterpret_cast<float2*>(C + (size_t)(r0 + 8) * 4096 + col) =
                    make_float2(acc[i][j][2] + b0, acc[i][j][3] + b1);
        }
    }
}

// ---------------- generic tiled SGEMM (used for small GRU GEMMs) -------------
__global__ void k_gemm(const float* __restrict__ A, const float* __restrict__ Bm,
                       const float* __restrict__ bias, float* __restrict__ C,
                       int M, int N, int K) {
    __shared__ float As[16][128];
    __shared__ float Bs[16][128];
    const int tid = threadIdx.x;
    const int bm = blockIdx.y * 128;
    const int bn = blockIdx.x * 128;
    const int tx = tid & 15, ty = tid >> 4;
    float acc[8][8];
    #pragma unroll
    for (int i = 0; i < 8; i++)
        #pragma unroll
        for (int j = 0; j < 8; j++) acc[i][j] = 0.f;

    for (int k0 = 0; k0 < K; k0 += 16) {
        #pragma unroll
        for (int l = 0; l < 2; l++) {
            int idx = tid + l * 256;
            int r = idx >> 2;
            int kq = (idx & 3) << 2;
            float4 v = make_float4(0.f, 0.f, 0.f, 0.f);
            int grow = bm + r;
            if (grow < M) v = *reinterpret_cast<const float4*>(A + (size_t)grow * K + k0 + kq);
            As[kq + 0][r] = v.x; As[kq + 1][r] = v.y;
            As[kq + 2][r] = v.z; As[kq + 3][r] = v.w;
        }
        #pragma unroll
        for (int l = 0; l < 2; l++) {
            int idx = tid + l * 256;
            int kr = idx >> 5;
            int c4 = (idx & 31) << 2;
            int gcol = bn + c4;
            float4 v = make_float4(0.f, 0.f, 0.f, 0.f);
            if (gcol < N) v = *reinterpret_cast<const float4*>(Bm + (size_t)(k0 + kr) * N + gcol);
            *reinterpret_cast<float4*>(&Bs[kr][c4]) = v;
        }
        __syncthreads();
        #pragma unroll
        for (int kk = 0; kk < 16; kk++) {
            float af[8], bf[8];
            *(float4*)&af[0] = *(const float4*)&As[kk][ty * 8];
            *(float4*)&af[4] = *(const float4*)&As[kk][ty * 8 + 4];
            *(float4*)&bf[0] = *(const float4*)&Bs[kk][tx * 8];
            *(float4*)&bf[4] = *(const float4*)&Bs[kk][tx * 8 + 4];
            #pragma unroll
            for (int i = 0; i < 8; i++)
                #pragma unroll
                for (int j = 0; j < 8; j++) acc[i][j] = fmaf(af[i], bf[j], acc[i][j]);
        }
        __syncthreads();
    }
    #pragma unroll
    for (int i = 0; i < 8; i++) {
        int grow = bm + ty * 8 + i;
        if (grow >= M) continue;
        #pragma unroll
        for (int j = 0; j < 8; j++) {
            int gcol = bn + tx * 8 + j;
            if (gcol < N) C[(size_t)grow * N + gcol] = acc[i][j] + bias[gcol];
        }
    }
}

// ---------------- per-edge message: msg[e]=feat[src[e]]@ew[e]; atomic agg ----
__global__ void k_msg(const int* __restrict__ ei, int E) {
    __shared__ float f_sh[4][DIM];
    int t = threadIdx.x;
    int eg = t >> 6, o = t & 63;
    int e = blockIdx.x * 4 + eg;
    if (e < E) {
        int src = ei[e];
        f_sh[eg][o] = g_h[(size_t)src * DIM + o];
    }
    __syncthreads();
    if (e >= E) return;
    const float* ew = &g_ew[(size_t)e * 4096 + o];
    const float* f = f_sh[eg];
    float acc = 0.f;
    #pragma unroll
    for (int i = 0; i < DIM; i++) acc = fmaf(f[i], ew[(size_t)i * DIM], acc);
    int dst = ei[E + e];
    atomicAdd(&g_agg[(size_t)dst * DIM + o], acc);
}

// ---------------- m = relu(agg*inv_deg + conv_b) -----------------------------
__global__ void k_mrelu(const float* __restrict__ conv_b, int N) {
    int idx = blockIdx.x * blockDim.x + threadIdx.x;
    if (idx >= N * DIM) return;
    int n = idx >> 6, d = idx & 63;
    g_m[idx] = fmaxf(fmaf(g_agg[idx], g_invdeg[n], conv_b[d]), 0.f);
}

// ---------------- GRU combine ------------------------------------------------
__global__ void k_gru_combine(int N) {
    int idx = blockIdx.x * blockDim.x + threadIdx.x;
    if (idx >= N * DIM) return;
    int n = idx >> 6, d = idx & 63;
    const float* gi = &g_gi[(size_t)n * 192];
    const float* gh = &g_gh[(size_t)n * 192];
    float r = sigf(gi[d] + gh[d]);
    float z = sigf(gi[64 + d] + gh[64 + d]);
    float nn = tanhf(fmaf(r, gh[128 + d], gi[128 + d]));
    float hold = g_h[idx];
    g_h[idx] = fmaf(z, hold - nn, nn);
}

// ---------------- graph segment offsets --------------------------------------
__global__ void k_seg_zero(int B, int N) {
    int b = threadIdx.x;
    if (b < B) { g_start[b] = 0x7fffffff; g_cnt[b] = 0; }
}
__global__ void k_seg_scan(const int* __restrict__ gidx, int N) {
    int n = blockIdx.x * blockDim.x + threadIdx.x;
    if (n >= N) return;
    int g = gidx[n];
    atomicMin(&g_start[g], n);
    atomicAdd(&g_cnt[g], 1);
}
__global__ void k_s2s_init(int B) {
    int i = blockIdx.x * blockDim.x + threadIdx.x;
    if (i < B * 128) g_qstar[i] = 0.f;
    if (i < B * DIM) { g_lh[i] = 0.f; g_lc[i] = 0.f; }
}

// ---------------- Set2Set LSTM step ------------------------------------------
__global__ void k_lstm(const float* __restrict__ bih, const float* __restrict__ bhh) {
    int b = blockIdx.x;
    int g = threadIdx.x;
    __shared__ float q_sh[128];
    __shared__ float h_sh[DIM];
    __shared__ float gates[256];
    if (g < 128) q_sh[g] = g_qstar[b * 128 + g];
    if (g < DIM) h_sh[g] = g_lh[b * DIM + g];
    __syncthreads();
    float acc = bih[g] + bhh[g];
    #pragma unroll 8
    for (int k = 0; k < 128; k++) acc = fmaf(q_sh[k], g_s2s_wihT[k * 256 + g], acc);
    #pragma unroll 8
    for (int k = 0; k < DIM; k++) acc = fmaf(h_sh[k], g_s2s_whhT[k * 256 + g], acc);
    gates[g] = acc;
    __syncthreads();
    if (g < DIM) {
        float i_g = sigf(gates[g]);
        float f_g = sigf(gates[64 + g]);
        float gg  = tanhf(gates[128 + g]);
        float o_g = sigf(gates[192 + g]);
        float c = fmaf(f_g, g_lc[b * DIM + g], i_g * gg);
        g_lc[b * DIM + g] = c;
        g_lh[b * DIM + g] = o_g * tanhf(c);
    }
}

// ---------------- Set2Set attention + readout --------------------------------
__global__ void k_attn(int B) {
    int b = blockIdx.x;
    int t = threadIdx.x;
    __shared__ float lh_sh[DIM];
    __shared__ float red[256];
    __shared__ float rpart[4][DIM];
    int s = g_start[b], c = g_cnt[b];
    if (t < DIM) lh_sh[t] = g_lh[b * DIM + t];
    __syncthreads();

    float lmax = -CUDART_INF_F;
    for (int n = s + t; n < s + c; n += 256) {
        const float* hp = &g_h[(size_t)n * DIM];
        float d = 0.f;
        #pragma unroll 8
        for (int k = 0; k < DIM; k++) d = fmaf(hp[k], lh_sh[k], d);
        g_e[n] = d;
        lmax = fmaxf(lmax, d);
    }
    red[t] = lmax;
    __syncthreads();
    for (int off = 128; off > 0; off >>= 1) {
        if (t < off) red[t] = fmaxf(red[t], red[t + off]);
        __syncthreads();
    }
    float emax = red[0];
    __syncthreads();

    float lsum = 0.f;
    for (int n = s + t; n < s + c; n += 256) lsum += expf(g_e[n] - emax);
    red[t] = lsum;
    __syncthreads();
    for (int off = 128; off > 0; off >>= 1) {
        if (t < off) red[t] += red[t + off];
        __syncthreads();
    }
    float asum = red[0];
    float inv = asum > 0.f ? 1.f / asum : 0.f;
    __syncthreads();

    int d = t & 63, sub = t >> 6;
    float acc = 0.f;
    for (int n = s + sub; n < s + c; n += 4)
        acc = fmaf(expf(g_e[n] - emax), g_h[(size_t)n * DIM + d], acc);
    rpart[sub][d] = acc;
    __syncthreads();
    if (t < DIM) {
        float r = (rpart[0][t] + rpart[1][t] + rpart[2][t] + rpart[3][t]) * inv;
        g_qstar[b * 128 + 64 + t] = r;
        g_qstar[b * 128 + t] = g_lh[b * DIM + t];
    }
}

// ---------------- FC head ----------------------------------------------------
__global__ void k_fc1(const float* __restrict__ w, const float* __restrict__ bias) {
    int b = blockIdx.x;
    int t = threadIdx.x;
    __shared__ float q_sh[128];
    q_sh[t] = g_qstar[b * 128 + t];
    q_sh[t + 64] = g_qstar[b * 128 + t + 64];
    __syncthreads();
    float acc = bias[t];
    #pragma unroll 8
    for (int k = 0; k < 128; k++) acc = fmaf(q_sh[k], w[k * DIM + t], acc);
    g_y[b * DIM + t] = fmaxf(acc, 0.f);
}
__global__ void k_fc2(const float* __restrict__ w, const float* __restrict__ bias,
                      float* __restrict__ out, int B) {
    int b = blockIdx.x * blockDim.x + threadIdx.x;
    if (b >= B) return;
    float acc = bias[0];
    #pragma unroll 8
    for (int k = 0; k < DIM; k++) acc = fmaf(g_y[b * DIM + k], w[k], acc);
    out[b] = acc;
}

// ---------------- launch -----------------------------------------------------
extern "C" void kernel_launch(void* const* d_in, const int* in_sizes, int n_in,
                              void* d_out, int out_size) {
    const int N = in_sizes[0] / 30;
    const int E = in_sizes[1] / 11;
    const int B = out_size;

    const float* nf   = (const float*)d_in[0];
    const float* ef   = (const float*)d_in[1];
    const int*   ei   = (const int*)d_in[2];
    const int*   gidx = (const int*)d_in[3];
    int wb = (in_sizes[4] == 1) ? 5 : 4;
    const float* lin0_w  = (const float*)d_in[wb + 0];
    const float* lin0_b  = (const float*)d_in[wb + 1];
    const float* enn_w1  = (const float*)d_in[wb + 2];
    const float* enn_b1  = (const float*)d_in[wb + 3];
    const float* enn_w2  = (const float*)d_in[wb + 4];
    const float* enn_b2  = (const float*)d_in[wb + 5];
    const float* conv_b  = (const float*)d_in[wb + 6];
    const float* gru_wih = (const float*)d_in[wb + 7];
    const float* gru_whh = (const float*)d_in[wb + 8];
    const float* gru_bih = (const float*)d_in[wb + 9];
    const float* gru_bhh = (const float*)d_in[wb + 10];
    const float* s2s_wih = (const float*)d_in[wb + 11];
    const float* s2s_whh = (const float*)d_in[wb + 12];
    const float* s2s_bih = (const float*)d_in[wb + 13];
    const float* s2s_bhh = (const float*)d_in[wb + 14];
    const float* fc1_w   = (const float*)d_in[wb + 15];
    const float* fc1_b   = (const float*)d_in[wb + 16];
    const float* fc2_w   = (const float*)d_in[wb + 17];
    const float* fc2_b   = (const float*)d_in[wb + 18];
    float* out = (float*)d_out;

    float *p_wihT, *p_whhT, *p_swihT, *p_swhhT, *p_ew, *p_h, *p_m, *p_gi, *p_gh, *p_agg;
    __nv_bfloat16 *p_a3, *p_b3;
    cudaGetSymbolAddress((void**)&p_wihT, g_wihT);
    cudaGetSymbolAddress((void**)&p_whhT, g_whhT);
    cudaGetSymbolAddress((void**)&p_swihT, g_s2s_wihT);
    cudaGetSymbolAddress((void**)&p_swhhT, g_s2s_whhT);
    cudaGetSymbolAddress((void**)&p_a3, g_a3);
    cudaGetSymbolAddress((void**)&p_b3, g_b3);
    cudaGetSymbolAddress((void**)&p_ew, g_ew);
    cudaGetSymbolAddress((void**)&p_h, g_h);
    cudaGetSymbolAddress((void**)&p_m, g_m);
    cudaGetSymbolAddress((void**)&p_gi, g_gi);
    cudaGetSymbolAddress((void**)&p_gh, g_gh);
    cudaGetSymbolAddress((void**)&p_agg, g_agg);
    int* p_deg; cudaGetSymbolAddress((void**)&p_deg, g_deg);

    // Launches 1-3: GEMM prerequisites. Launch 4 is the big GEMM (ncu
    // empirically profiles the 4th launch: R1=transpose, R2=k_count).
    k_enn1<<<(E * 128 + 255) / 256, 256>>>(ef, enn_w1, enn_b1, E);
    k_prep_b<<<(128 * 4096 + 255) / 256, 256>>>(enn_w2);
    k_lin0<<<(N * DIM + 255) / 256, 256>>>(nf, lin0_w, lin0_b, N);
    {
        dim3 grid(4096 / 128, (E + 127) / 128);
        k_gemm_bf16<<<grid, 256>>>(p_a3, p_b3, enn_b2, p_ew, E);
    }

    // degrees + weight transposes
    k_zero_i<<<(N + 255) / 256, 256>>>(p_deg, N);
    k_count<<<(E + 255) / 256, 256>>>(ei, E);
    k_invdeg<<<(N + 255) / 256, 256>>>(N);
    k_transpose<<<(192 * 64 + 255) / 256, 256>>>(p_wihT, gru_wih, 192, 64);
    k_transpose<<<(192 * 64 + 255) / 256, 256>>>(p_whhT, gru_whh, 192, 64);
    k_transpose<<<(256 * 128 + 255) / 256, 256>>>(p_swihT, s2s_wih, 256, 128);
    k_transpose<<<(256 * 64 + 255) / 256, 256>>>(p_swhhT, s2s_whh, 256, 64);

    // 3 message-passing + GRU iterations
    for (int it = 0; it < 3; it++) {
        k_zero_f<<<(N * DIM + 255) / 256, 256>>>(p_agg, N * DIM);
        k_msg<<<(E + 3) / 4, 256>>>(ei, E);
        k_mrelu<<<(N * DIM + 255) / 256, 256>>>(conv_b, N);
        {
            dim3 grid((192 + 127) / 128, (N + 127) / 128);
            k_gemm<<<grid, 256>>>(p_m, p_wihT, gru_bih, p_gi, N, 192, 64);
            k_gemm<<<grid, 256>>>(p_h, p_whhT, gru_bhh, p_gh, N, 192, 64);
        }
        k_gru_combine<<<(N * DIM + 255) / 256, 256>>>(N);
    }

    // Set2Set
    k_seg_zero<<<1, 128>>>(B, N);
    k_seg_scan<<<(N + 255) / 256, 256>>>(gidx, N);
    k_s2s_init<<<(B * 128 + 255) / 256, 256>>>(B);
    for (int it = 0; it < 3; it++) {
        k_lstm<<<B, 256>>>(s2s_bih, s2s_bhh);
        k_attn<<<B, 256>>>(B);
    }

    // FC head
    k_fc1<<<B, 64>>>(fc1_w, fc1_b);
    k_fc2<<<(B + 127) / 128, 128>>>(fc2_w, fc2_b, out, B);
}

// round 6
// speedup vs baseline: 1.4313x; 1.0089x over previous
#include <cuda_runtime.h>
#include <cuda_bf16.h>
#include <cstdint>
#include <math_constants.h>

// ---------------- problem-size capacities (fixed by the dataset) -------------
#define NMAX 20000
#define EMAX 30000
#define BMAX 128
#define DIM  64

// ---------------- device scratch (static: no allocations allowed) ------------
__device__ __align__(256) float g_h[NMAX * DIM];
__device__ __align__(256) float g_agg[NMAX * DIM];
__device__ __align__(256) __nv_bfloat16 g_a3[(size_t)(EMAX + 256) * 384]; // [E,384]: a0|a0|a1
__device__ __align__(256) __nv_bfloat16 g_b3[(size_t)384 * 4096];         // [384,4096]: b0;b1;b0
__device__ __align__(256) float g_ew[(size_t)EMAX * 4096];  // per-edge 64x64 (491MB)
__device__ int   g_deg[NMAX];
__device__ float g_invdeg[NMAX];
__device__ __align__(256) float g_gruw[128 * 192];          // stacked GRU weights [128][192]
__device__ __align__(256) float g_s2s_wihT[128 * 256];      // transposed LSTM weights
__device__ __align__(256) float g_s2s_whhT[DIM * 256];
__device__ float g_e[NMAX];
__device__ int   g_start[BMAX];
__device__ int   g_cnt[BMAX];

__device__ __forceinline__ float sigf(float x) { return 1.f / (1.f + expf(-x)); }

// ---------------- small utility kernels --------------------------------------
__global__ void k_zero_f(float* p, int n) {
    int i = blockIdx.x * blockDim.x + threadIdx.x;
    if (i < n) p[i] = 0.f;
}
__global__ void k_zero_i(int* p, int n) {
    int i = blockIdx.x * blockDim.x + threadIdx.x;
    if (i < n) p[i] = 0;
}
__global__ void k_transpose(float* dst, const float* __restrict__ src, int G, int K) {
    int idx = blockIdx.x * blockDim.x + threadIdx.x;
    if (idx >= G * K) return;
    int g = idx / K, k = idx % K;
    dst[k * G + g] = src[idx];
}
// stacked GRU weight: g_gruw[k][g] = k<64 ? wih[g][k] : whh[g][k-64]
__global__ void k_prep_gru(const float* __restrict__ wih, const float* __restrict__ whh) {
    int idx = blockIdx.x * blockDim.x + threadIdx.x;
    if (idx >= 128 * 192) return;
    int k = idx / 192, g = idx % 192;
    g_gruw[idx] = (k < 64) ? wih[g * 64 + k] : whh[g * 64 + (k - 64)];
}

// ---------------- lin0: h = relu(nf @ W + b)  [N,30]@[30,64] ------------------
__global__ void k_lin0(const float* __restrict__ nf, const float* __restrict__ w,
                       const float* __restrict__ b, int N) {
    int idx = blockIdx.x * blockDim.x + threadIdx.x;
    if (idx >= N * DIM) return;
    int n = idx >> 6, d = idx & 63;
    float acc = b[d];
    #pragma unroll
    for (int k = 0; k < 30; k++) acc = fmaf(nf[n * 30 + k], w[k * DIM + d], acc);
    g_h[idx] = fmaxf(acc, 0.f);
}

// ---------------- ENN hidden with bf16x3 split: a=relu(ef@W1+b1), A*=[a0|a0|a1]
__global__ void k_enn1(const float* __restrict__ ef, const float* __restrict__ w1,
                       const float* __restrict__ b1, int E) {
    int idx = blockIdx.x * blockDim.x + threadIdx.x;
    if (idx >= E * 128) return;
    int e = idx >> 7, j = idx & 127;
    float acc = b1[j];
    #pragma unroll
    for (int k = 0; k < 11; k++) acc = fmaf(ef[e * 11 + k], w1[k * 128 + j], acc);
    acc = fmaxf(acc, 0.f);
    __nv_bfloat16 a0 = __float2bfloat16(acc);
    __nv_bfloat16 a1 = __float2bfloat16(acc - __bfloat162float(a0));
    size_t base = (size_t)e * 384;
    g_a3[base + j] = a0;
    g_a3[base + 128 + j] = a0;
    g_a3[base + 256 + j] = a1;
}

// ---------------- B* prep: [b0; b1; b0] from W2 [128,4096] -------------------
__global__ void k_prep_b(const float* __restrict__ w2) {
    int idx = blockIdx.x * blockDim.x + threadIdx.x;
    if (idx >= 128 * 4096) return;
    float w = w2[idx];
    __nv_bfloat16 b0 = __float2bfloat16(w);
    __nv_bfloat16 b1 = __float2bfloat16(w - __bfloat162float(b0));
    int row = idx >> 12, col = idx & 4095;
    g_b3[(size_t)row * 4096 + col] = b0;
    g_b3[(size_t)(128 + row) * 4096 + col] = b1;
    g_b3[(size_t)(256 + row) * 4096 + col] = b0;
}

// ---------------- degrees ----------------------------------------------------
__global__ void k_count(const int* __restrict__ ei, int E) {
    int e = blockIdx.x * blockDim.x + threadIdx.x;
    if (e < E) atomicAdd(&g_deg[ei[E + e]], 1);
}
__global__ void k_invdeg(int N) {
    int n = blockIdx.x * blockDim.x + threadIdx.x;
    if (n < N) g_invdeg[n] = 1.f / fmaxf((float)g_deg[n], 1.f);
}

// ---------------- bf16 tensor-core GEMM (VERBATIM from verified R3) ----------
// A [M,384] bf16 row-major (bf16x3-split), B [384,4096] bf16 row-major,
// C [M,4096] fp32. Block 128x128, BK=32, 256 thr = 8 warps (2x4), warp 64x32.
__global__ void __launch_bounds__(256) k_gemm_bf16(
        const __nv_bfloat16* __restrict__ A, const __nv_bfloat16* __restrict__ Bm,
        const float* __restrict__ bias, float* __restrict__ C, int M) {
    __shared__ __align__(16) unsigned Af[2][8][2][33][4];  // [buf][mt][kt][lane(+pad)][reg]
    __shared__ __align__(16) unsigned Bf[2][2][16][33][2]; // [buf][kt][nt][lane(+pad)][reg]
    const int tid = threadIdx.x;
    const int lane = tid & 31, warp = tid >> 5;
    const int wm = warp >> 2, wn = warp & 3;
    const int bm = blockIdx.y << 7, bn = blockIdx.x << 7;

    float acc[4][4][4];
    #pragma unroll
    for (int i = 0; i < 4; i++)
        #pragma unroll
        for (int j = 0; j < 4; j++)
            #pragma unroll
            for (int c = 0; c < 4; c++) acc[i][j][c] = 0.f;

    uint4 ra[2];
    uint2 rb[2][2];

    auto LDG = [&](int s) {
        int k0 = s << 5;
        #pragma unroll
        for (int l = 0; l < 2; l++) {
            int idx = tid + (l << 8);
            int r = idx >> 2, kq = (idx & 3) << 3;
            if (bm + r < M)
                ra[l] = *reinterpret_cast<const uint4*>(A + (size_t)(bm + r) * 384 + k0 + kq);
            else
                ra[l] = make_uint4(0u, 0u, 0u, 0u);
            int kp = idx >> 5, c4 = (idx & 31) << 2;
            const __nv_bfloat16* p = Bm + (size_t)(k0 + 2 * kp) * 4096 + bn + c4;
            rb[l][0] = *reinterpret_cast<const uint2*>(p);
            rb[l][1] = *reinterpret_cast<const uint2*>(p + 4096);
        }
    };
    auto STS = [&](int buf) {
        #pragma unroll
        for (int l = 0; l < 2; l++) {
            {
                int idx = tid + (l << 8);
                int r = idx >> 2, kq = (idx & 3) << 3;
                int mt = r >> 4, r16 = r & 15;
                int kt = kq >> 4;
                int reg = (r16 >> 3) + (((kq >> 3) & 1) << 1);
                int ln0 = (r16 & 7) << 2;
                unsigned* dst = &Af[buf][mt][kt][0][0];
                dst[(ln0 + 0) * 4 + reg] = ra[l].x;
                dst[(ln0 + 1) * 4 + reg] = ra[l].y;
                dst[(ln0 + 2) * 4 + reg] = ra[l].z;
                dst[(ln0 + 3) * 4 + reg] = ra[l].w;
            }
            {
                int idx = tid + (l << 8);
                int kp = idx >> 5, c4 = (idx & 31) << 2;
                int ktb = kp >> 3, t = kp & 3, regb = (kp >> 2) & 1;
                unsigned u[4];
                u[0] = (rb[l][0].x & 0xFFFFu) | (rb[l][1].x << 16);
                u[1] = (rb[l][0].x >> 16) | (rb[l][1].x & 0xFFFF0000u);
                u[2] = (rb[l][0].y & 0xFFFFu) | (rb[l][1].y << 16);
                u[3] = (rb[l][0].y >> 16) | (rb[l][1].y & 0xFFFF0000u);
                #pragma unroll
                for (int j = 0; j < 4; j++) {
                    int n = c4 + j;
                    Bf[buf][ktb][n >> 3][((n & 7) << 2) + t][regb] = u[j];
                }
            }
        }
    };
    auto COMPUTE = [&](int buf) {
        #pragma unroll
        for (int kt = 0; kt < 2; kt++) {
            unsigned a[4][4], b[4][2];
            #pragma unroll
            for (int i = 0; i < 4; i++)
                *reinterpret_cast<uint4*>(a[i]) =
                    *reinterpret_cast<const uint4*>(&Af[buf][(wm << 2) + i][kt][lane][0]);
            #pragma unroll
            for (int j = 0; j < 4; j++)
                *reinterpret_cast<uint2*>(b[j]) =
                    *reinterpret_cast<const uint2*>(&Bf[buf][kt][(wn << 2) + j][lane][0]);
            #pragma unroll
            for (int i = 0; i < 4; i++)
                #pragma unroll
                for (int j = 0; j < 4; j++)
                    asm volatile(
                        "mma.sync.aligned.m16n8k16.row.col.f32.bf16.bf16.f32 "
                        "{%0,%1,%2,%3}, {%4,%5,%6,%7}, {%8,%9}, {%0,%1,%2,%3};"
                        : "+f"(acc[i][j][0]), "+f"(acc[i][j][1]),
                          "+f"(acc[i][j][2]), "+f"(acc[i][j][3])
                        : "r"(a[i][0]), "r"(a[i][1]), "r"(a[i][2]), "r"(a[i][3]),
                          "r"(b[j][0]), "r"(b[j][1]));
        }
    };

    LDG(0);
    STS(0);
    __syncthreads();
    #pragma unroll 1
    for (int s = 0; s < 12; s++) {
        if (s < 11) LDG(s + 1);
        COMPUTE(s & 1);
        if (s < 11) {
            STS((s + 1) & 1);
            __syncthreads();
        }
    }

    int g = lane >> 2, tg = lane & 3;
    #pragma unroll
    for (int i = 0; i < 4; i++) {
        int r0 = bm + (wm << 6) + (i << 4) + g;
        #pragma unroll
        for (int j = 0; j < 4; j++) {
            int col = bn + (wn << 5) + (j << 3) + (tg << 1);
            float b0 = bias[col], b1 = bias[col + 1];
            if (r0 < M)
                *reinterpret_cast<float2*>(C + (size_t)r0 * 4096 + col) =
                    make_float2(acc[i][j][0] + b0, acc[i][j][1] + b1);
            if (r0 + 8 < M)
                *reinterpret_cast<float2*>(C + (size_t)(r0 + 8) * 4096 + col) =
                    make_float2(acc[i][j][2] + b0, acc[i][j][3] + b1);
        }
    }
}

// ---------------- per-edge message: msg[e]=feat[src[e]]@ew[e]; atomic agg ----
__global__ void k_msg(const int* __restrict__ ei, int E) {
    __shared__ float f_sh[4][DIM];
    int t = threadIdx.x;
    int eg = t >> 6, o = t & 63;
    int e = blockIdx.x * 4 + eg;
    if (e < E) {
        int src = ei[e];
        f_sh[eg][o] = g_h[(size_t)src * DIM + o];
    }
    __syncthreads();
    if (e >= E) return;
    const float* ew = &g_ew[(size_t)e * 4096 + o];
    const float* f = f_sh[eg];
    float acc = 0.f;
    #pragma unroll
    for (int i = 0; i < DIM; i++) acc = fmaf(f[i], ew[(size_t)i * DIM], acc);
    int dst = ei[E + e];
    atomicAdd(&g_agg[(size_t)dst * DIM + o], acc);
}

// ---------------- fused GRU: m=relu(agg*inv+b); h=GRU(m,h) -------------------
// One warp per node. Weights [128][192] in smem. Gate g = lane + 32*c.
__global__ void k_gru_fused(const float* __restrict__ bih, const float* __restrict__ bhh,
                            const float* __restrict__ conv_b, int N) {
    extern __shared__ float sw[];            // 128*192 weights + 8*128 node bufs
    float* nb = sw + 128 * 192;
    for (int i = threadIdx.x; i < 128 * 192; i += 256) sw[i] = g_gruw[i];
    __syncthreads();
    int warp = threadIdx.x >> 5, lane = threadIdx.x & 31;
    float* in = nb + warp * 128;
    for (int n = blockIdx.x * 8 + warp; n < N; n += gridDim.x * 8) {
        float inv = g_invdeg[n];
        #pragma unroll
        for (int j = lane; j < 64; j += 32) {
            in[j] = fmaxf(fmaf(g_agg[n * 64 + j], inv, conv_b[j]), 0.f);
            in[64 + j] = g_h[n * 64 + j];
        }
        __syncwarp();
        float accrz[4];
        #pragma unroll
        for (int c = 0; c < 4; c++) {
            int g = lane + 32 * c;
            float a = bih[g] + bhh[g];
            #pragma unroll 16
            for (int k = 0; k < 128; k++) a = fmaf(in[k], sw[k * 192 + g], a);
            accrz[c] = a;
        }
        float ni[2], nh[2];
        #pragma unroll
        for (int c = 0; c < 2; c++) {
            int g = 128 + lane + 32 * c;
            float ai = bih[g], ah = bhh[g];
            #pragma unroll 16
            for (int k = 0; k < 64; k++) ai = fmaf(in[k], sw[k * 192 + g], ai);
            #pragma unroll 16
            for (int k = 64; k < 128; k++) ah = fmaf(in[k], sw[k * 192 + g], ah);
            ni[c] = ai; nh[c] = ah;
        }
        #pragma unroll
        for (int c = 0; c < 2; c++) {
            int d = lane + 32 * c;
            float r = sigf(accrz[c]);
            float z = sigf(accrz[2 + c]);
            float nn = tanhf(fmaf(r, nh[c], ni[c]));
            float hold = in[64 + d];
            g_h[n * 64 + d] = fmaf(z, hold - nn, nn);
        }
        __syncwarp();
    }
}

// ---------------- graph segment offsets --------------------------------------
__global__ void k_seg_zero(int B) {
    int b = threadIdx.x;
    if (b < B) { g_start[b] = 0x7fffffff; g_cnt[b] = 0; }
}
__global__ void k_seg_scan(const int* __restrict__ gidx, int N) {
    int n = blockIdx.x * blockDim.x + threadIdx.x;
    if (n >= N) return;
    int g = gidx[n];
    atomicMin(&g_start[g], n);
    atomicAdd(&g_cnt[g], 1);
}

// ---------------- fused Set2Set (3 steps) + FC head: one block per graph -----
__global__ void k_s2s_all(const float* __restrict__ bih, const float* __restrict__ bhh,
                          const float* __restrict__ fc1_w, const float* __restrict__ fc1_b,
                          const float* __restrict__ fc2_w, const float* __restrict__ fc2_b,
                          float* __restrict__ out) {
    int b = blockIdx.x, t = threadIdx.x;    // 256 threads
    __shared__ float q_sh[128], h_sh[64], lc_sh[64], gates[256], red[256], rpart[4][64];
    if (t < 128) q_sh[t] = 0.f;
    if (t < 64) { h_sh[t] = 0.f; lc_sh[t] = 0.f; }
    int s = g_start[b], c = g_cnt[b];
    if (s == 0x7fffffff) s = 0;              // empty-graph guard
    __syncthreads();
    for (int step = 0; step < 3; step++) {
        float acc = bih[t] + bhh[t];
        #pragma unroll 8
        for (int k = 0; k < 128; k++) acc = fmaf(q_sh[k], g_s2s_wihT[k * 256 + t], acc);
        #pragma unroll 8
        for (int k = 0; k < 64; k++) acc = fmaf(h_sh[k], g_s2s_whhT[k * 256 + t], acc);
        gates[t] = acc;
        __syncthreads();
        if (t < 64) {
            float ig = sigf(gates[t]), fg = sigf(gates[64 + t]);
            float gg = tanhf(gates[128 + t]), og = sigf(gates[192 + t]);
            float cc = fmaf(fg, lc_sh[t], ig * gg);
            lc_sh[t] = cc;
            h_sh[t] = og * tanhf(cc);
        }
        __syncthreads();
        float lmax = -CUDART_INF_F;
        for (int n = s + t; n < s + c; n += 256) {
            const float* hp = &g_h[(size_t)n * DIM];
            float d = 0.f;
            #pragma unroll 8
            for (int k = 0; k < DIM; k++) d = fmaf(hp[k], h_sh[k], d);
            g_e[n] = d;
            lmax = fmaxf(lmax, d);
        }
        red[t] = lmax;
        __syncthreads();
        for (int off = 128; off > 0; off >>= 1) {
            if (t < off) red[t] = fmaxf(red[t], red[t + off]);
            __syncthreads();
        }
        float emax = red[0];
        __syncthreads();
        float lsum = 0.f;
        for (int n = s + t; n < s + c; n += 256) lsum += expf(g_e[n] - emax);
        red[t] = lsum;
        __syncthreads();
        for (int off = 128; off > 0; off >>= 1) {
            if (t < off) red[t] += red[t + off];
            __syncthreads();
        }
        float inv = red[0] > 0.f ? 1.f / red[0] : 0.f;
        __syncthreads();
        int d = t & 63, sub = t >> 6;
        float acc2 = 0.f;
        for (int n = s + sub; n < s + c; n += 4)
            acc2 = fmaf(expf(g_e[n] - emax), g_h[(size_t)n * DIM + d], acc2);
        rpart[sub][d] = acc2;
        __syncthreads();
        if (t < 64) {
            q_sh[64 + t] = (rpart[0][t] + rpart[1][t] + rpart[2][t] + rpart[3][t]) * inv;
            q_sh[t] = h_sh[t];
        }
        __syncthreads();
    }
    if (t < 64) {
        float acc = fc1_b[t];
        #pragma unroll 8
        for (int k = 0; k < 128; k++) acc = fmaf(q_sh[k], fc1_w[k * DIM + t], acc);
        red[t] = fmaxf(acc, 0.f) * fc2_w[t];
    }
    __syncthreads();
    for (int off = 32; off > 0; off >>= 1) {
        if (t < off) red[t] += red[t + off];
        __syncthreads();
    }
    if (t == 0) out[b] = red[0] + fc2_b[0];
}

// ---------------- launch -----------------------------------------------------
extern "C" void kernel_launch(void* const* d_in, const int* in_sizes, int n_in,
                              void* d_out, int out_size) {
    const int N = in_sizes[0] / 30;
    const int E = in_sizes[1] / 11;
    const int B = out_size;

    const float* nf   = (const float*)d_in[0];
    const float* ef   = (const float*)d_in[1];
    const int*   ei   = (const int*)d_in[2];
    const int*   gidx = (const int*)d_in[3];
    int wb = (in_sizes[4] == 1) ? 5 : 4;
    const float* lin0_w  = (const float*)d_in[wb + 0];
    const float* lin0_b  = (const float*)d_in[wb + 1];
    const float* enn_w1  = (const float*)d_in[wb + 2];
    const float* enn_b1  = (const float*)d_in[wb + 3];
    const float* enn_w2  = (const float*)d_in[wb + 4];
    const float* enn_b2  = (const float*)d_in[wb + 5];
    const float* conv_b  = (const float*)d_in[wb + 6];
    const float* gru_wih = (const float*)d_in[wb + 7];
    const float* gru_whh = (const float*)d_in[wb + 8];
    const float* gru_bih = (const float*)d_in[wb + 9];
    const float* gru_bhh = (const float*)d_in[wb + 10];
    const float* s2s_wih = (const float*)d_in[wb + 11];
    const float* s2s_whh = (const float*)d_in[wb + 12];
    const float* s2s_bih = (const float*)d_in[wb + 13];
    const float* s2s_bhh = (const float*)d_in[wb + 14];
    const float* fc1_w   = (const float*)d_in[wb + 15];
    const float* fc1_b   = (const float*)d_in[wb + 16];
    const float* fc2_w   = (const float*)d_in[wb + 17];
    const float* fc2_b   = (const float*)d_in[wb + 18];
    float* out = (float*)d_out;

    float *p_swihT, *p_swhhT, *p_ew, *p_agg;
    __nv_bfloat16 *p_a3, *p_b3;
    cudaGetSymbolAddress((void**)&p_swihT, g_s2s_wihT);
    cudaGetSymbolAddress((void**)&p_swhhT, g_s2s_whhT);
    cudaGetSymbolAddress((void**)&p_a3, g_a3);
    cudaGetSymbolAddress((void**)&p_b3, g_b3);
    cudaGetSymbolAddress((void**)&p_ew, g_ew);
    cudaGetSymbolAddress((void**)&p_agg, g_agg);
    int* p_deg; cudaGetSymbolAddress((void**)&p_deg, g_deg);

    cudaFuncSetAttribute(k_gru_fused, cudaFuncAttributeMaxDynamicSharedMemorySize, 102400);

    // Launches 1-3 prereqs; launch 4 = big GEMM (ncu profiles the 4th launch)
    k_enn1<<<(E * 128 + 255) / 256, 256>>>(ef, enn_w1, enn_b1, E);
    k_prep_b<<<(128 * 4096 + 255) / 256, 256>>>(enn_w2);
    k_lin0<<<(N * DIM + 255) / 256, 256>>>(nf, lin0_w, lin0_b, N);
    {
        dim3 grid(4096 / 128, (E + 127) / 128);
        k_gemm_bf16<<<grid, 256>>>(p_a3, p_b3, enn_b2, p_ew, E);
    }

    // degrees + weight preps
    k_prep_gru<<<(128 * 192 + 255) / 256, 256>>>(gru_wih, gru_whh);
    k_zero_i<<<(N + 255) / 256, 256>>>(p_deg, N);
    k_count<<<(E + 255) / 256, 256>>>(ei, E);
    k_invdeg<<<(N + 255) / 256, 256>>>(N);
    k_transpose<<<(256 * 128 + 255) / 256, 256>>>(p_swihT, s2s_wih, 256, 128);
    k_transpose<<<(256 * 64 + 255) / 256, 256>>>(p_swhhT, s2s_whh, 256, 64);

    // 3 message-passing + GRU iterations
    for (int it = 0; it < 3; it++) {
        k_zero_f<<<(N * DIM + 255) / 256, 256>>>(p_agg, N * DIM);
        k_msg<<<(E + 3) / 4, 256>>>(ei, E);
        k_gru_fused<<<148, 256, 102400>>>(gru_bih, gru_bhh, conv_b, N);
    }

    // Set2Set + FC head
    k_seg_zero<<<1, 128>>>(B);
    k_seg_scan<<<(N + 255) / 256, 256>>>(gidx, N);
    k_s2s_all<<<B, 256>>>(s2s_bih, s2s_bhh, fc1_w, fc1_b, fc2_w, fc2_b, out);
}

// round 7
// speedup vs baseline: 1.6665x; 1.1643x over previous
#include <cuda_runtime.h>
#include <cuda_bf16.h>
#include <cuda_fp16.h>
#include <cstdint>
#include <math_constants.h>

// ---------------- problem-size capacities (fixed by the dataset) -------------
#define NMAX 20000
#define EMAX 30000
#define BMAX 128
#define DIM  64

// ---------------- device scratch (static: no allocations allowed) ------------
__device__ __align__(256) float g_h[NMAX * DIM];
__device__ __align__(256) float g_agg[NMAX * DIM];
// A* pre-packed in mma fragment order: [m16][k16][lane][reg], m16<1888, k16<24
__device__ __align__(256) unsigned g_apack[(size_t)1888 * 24 * 128];
// B* pre-packed in mma fragment order: [k16][n8][lane][reg], k16<24, n8<512
__device__ __align__(256) unsigned g_bpack[(size_t)24 * 512 * 64];
__device__ __align__(256) __half g_ew16[(size_t)EMAX * 4096];   // per-edge 64x64 (fp16, 245MB)
__device__ int   g_deg[NMAX];
__device__ float g_invdeg[NMAX];
__device__ __align__(256) float g_gruw[128 * 192];
__device__ __align__(256) float g_s2s_wihT[128 * 256];
__device__ __align__(256) float g_s2s_whhT[DIM * 256];
__device__ float g_e[NMAX];
__device__ int   g_start[BMAX];
__device__ int   g_cnt[BMAX];

__device__ __forceinline__ float sigf(float x) { return 1.f / (1.f + expf(-x)); }
__device__ __forceinline__ unsigned bfpack(float lo, float hi) {
    __nv_bfloat16 l = __float2bfloat16(lo), h = __float2bfloat16(hi);
    return (unsigned)__bfloat16_as_ushort(l) | ((unsigned)__bfloat16_as_ushort(h) << 16);
}

// ---------------- small utility kernels --------------------------------------
__global__ void k_zero_f(float* p, int n) {
    int i = blockIdx.x * blockDim.x + threadIdx.x;
    if (i < n) p[i] = 0.f;
}
__global__ void k_zero_i(int* p, int n) {
    int i = blockIdx.x * blockDim.x + threadIdx.x;
    if (i < n) p[i] = 0;
}
__global__ void k_transpose(float* dst, const float* __restrict__ src, int G, int K) {
    int idx = blockIdx.x * blockDim.x + threadIdx.x;
    if (idx >= G * K) return;
    int g = idx / K, k = idx % K;
    dst[k * G + g] = src[idx];
}
__global__ void k_prep_gru(const float* __restrict__ wih, const float* __restrict__ whh) {
    int idx = blockIdx.x * blockDim.x + threadIdx.x;
    if (idx >= 128 * 192) return;
    int k = idx / 192, g = idx % 192;
    g_gruw[idx] = (k < 64) ? wih[g * 64 + k] : whh[g * 64 + (k - 64)];
}

// ---------------- lin0: h = relu(nf @ W + b)  [N,30]@[30,64] ------------------
__global__ void k_lin0(const float* __restrict__ nf, const float* __restrict__ w,
                       const float* __restrict__ b, int N) {
    int idx = blockIdx.x * blockDim.x + threadIdx.x;
    if (idx >= N * DIM) return;
    int n = idx >> 6, d = idx & 63;
    float acc = b[d];
    #pragma unroll
    for (int k = 0; k < 30; k++) acc = fmaf(nf[n * 30 + k], w[k * DIM + d], acc);
    g_h[idx] = fmaxf(acc, 0.f);
}

// ------- ENN hidden producing fragment-ordered A*: a=relu(ef@W1+b1) ----------
// A* logical [E,384] = [a0 | a0 | a1]; one thread computes a j-pair (2 cols).
__global__ void k_enn1(const float* __restrict__ ef, const float* __restrict__ w1,
                       const float* __restrict__ b1, int E) {
    int idx = blockIdx.x * blockDim.x + threadIdx.x;
    if (idx >= E * 64) return;
    int e = idx >> 6, jp = idx & 63;
    int j0 = jp << 1;
    float f[11];
    #pragma unroll
    for (int k = 0; k < 11; k++) f[k] = ef[e * 11 + k];
    float a = b1[j0], b = b1[j0 + 1];
    #pragma unroll
    for (int k = 0; k < 11; k++) {
        a = fmaf(f[k], w1[k * 128 + j0], a);
        b = fmaf(f[k], w1[k * 128 + j0 + 1], b);
    }
    a = fmaxf(a, 0.f);
    b = fmaxf(b, 0.f);
    float a0 = __bfloat162float(__float2bfloat16(a));
    float b0 = __bfloat162float(__float2bfloat16(b));
    unsigned p0 = bfpack(a, b);                 // hi parts
    unsigned p1 = bfpack(a - a0, b - b0);       // residuals
    int m16 = e >> 4, r16 = e & 15;
    int k8 = j0 & 15;
    int lane = ((r16 & 7) << 2) | ((k8 >> 1) & 3);
    int reg = (r16 >> 3) | (((k8 >> 3) & 1) << 1);
    // k = j0 -> k16 = j0>>4 ; k = j0+128 -> +8 ; k = j0+256 -> +16 (k8 identical)
    size_t base = ((size_t)m16 * 24 + (j0 >> 4)) * 128 + lane * 4 + reg;
    g_apack[base] = p0;
    g_apack[base + (size_t)8 * 128] = p0;
    g_apack[base + (size_t)16 * 128] = p1;
}

// ------- B* prep into fragment order: logical [384,4096] = [b0;b1;b0] --------
__global__ void k_prep_b(const float* __restrict__ w2) {
    int idx = blockIdx.x * blockDim.x + threadIdx.x;
    if (idx >= 192 * 4096) return;
    int kp = idx >> 12;          // pair index 0..191 -> K* = 2*kp
    int n = idx & 4095;
    int Ks = kp << 1;
    int region = Ks >> 7;        // 0: b0, 1: b1, 2: b0
    int k = Ks & 127;
    float wa = w2[k * 4096 + n], wb = w2[(k + 1) * 4096 + n];
    float va, vb;
    if (region == 1) {
        va = wa - __bfloat162float(__float2bfloat16(wa));
        vb = wb - __bfloat162float(__float2bfloat16(wb));
    } else {
        va = wa; vb = wb;
    }
    unsigned u = bfpack(va, vb);
    int k16 = Ks >> 4, k8 = Ks & 15;
    int lane = ((n & 7) << 2) | ((k8 >> 1) & 3);
    int reg = (k8 >> 3) & 1;
    g_bpack[((k16 * 512 + (n >> 3)) * 32 + lane) * 2 + reg] = u;
}

// ---------------- degrees ----------------------------------------------------
__global__ void k_count(const int* __restrict__ ei, int E) {
    int e = blockIdx.x * blockDim.x + threadIdx.x;
    if (e < E) atomicAdd(&g_deg[ei[E + e]], 1);
}
__global__ void k_invdeg(int N) {
    int n = blockIdx.x * blockDim.x + threadIdx.x;
    if (n < N) g_invdeg[n] = 1.f / fmaxf((float)g_deg[n], 1.f);
}

// ---------------- bf16 tensor-core GEMM, operands pre-packed in gmem ---------
// C[M,4096] fp16 = A*@B* + bias. Block 128x128, 12 stages of K=32.
// LOAD = identity uint4 copies (fragment order); COMPUTE = verified R3 path.
__global__ void __launch_bounds__(256) k_gemm_bf16(
        const unsigned* __restrict__ Ap, const unsigned* __restrict__ Bp,
        const float* __restrict__ bias, __half* __restrict__ C, int M) {
    __shared__ __align__(16) unsigned Af[2][8][2][32][4];  // [buf][mt][kt][lane][reg]
    __shared__ __align__(16) unsigned Bf[2][2][16][32][2]; // [buf][kt][nt][lane][reg]
    const int tid = threadIdx.x;
    const int lane = tid & 31, warp = tid >> 5;
    const int wm = warp >> 2, wn = warp & 3;
    const int bm = blockIdx.y << 7, bn = blockIdx.x << 7;
    const uint4* Ap4 = reinterpret_cast<const uint4*>(Ap);
    const uint4* Bp4 = reinterpret_cast<const uint4*>(Bp);

    float acc[4][4][4];
    #pragma unroll
    for (int i = 0; i < 4; i++)
        #pragma unroll
        for (int j = 0; j < 4; j++)
            #pragma unroll
            for (int c = 0; c < 4; c++) acc[i][j][c] = 0.f;

    uint4 ra[2], rb[2];

    auto LDG = [&](int s) {
        #pragma unroll
        for (int l = 0; l < 2; l++) {
            {   // A: 512 uint4 per stage; id -> (mt, kt, lane)
                int id = tid + (l << 8);
                int la = id & 31, kt = (id >> 5) & 1, mt = id >> 6;
                ra[l] = Ap4[(((size_t)((bm >> 4) + mt)) * 24 + (s * 2 + kt)) * 32 + la];
            }
            {   // B: 512 uint4 per stage; id -> (kt, nt, quad)
                int id = tid + (l << 8);
                int quad = id & 15, nt = (id >> 4) & 15, kt = id >> 8;
                rb[l] = Bp4[((size_t)(s * 2 + kt) * 512 + (bn >> 3) + nt) * 16 + quad];
            }
        }
    };
    auto STS = [&](int buf) {
        #pragma unroll
        for (int l = 0; l < 2; l++) {
            {
                int id = tid + (l << 8);
                int la = id & 31, kt = (id >> 5) & 1, mt = id >> 6;
                *reinterpret_cast<uint4*>(&Af[buf][mt][kt][la][0]) = ra[l];
            }
            {
                int id = tid + (l << 8);
                int quad = id & 15, nt = (id >> 4) & 15, kt = id >> 8;
                *reinterpret_cast<uint4*>(&Bf[buf][kt][nt][quad * 2][0]) = rb[l];
            }
        }
    };
    auto COMPUTE = [&](int buf) {
        #pragma unroll
        for (int kt = 0; kt < 2; kt++) {
            unsigned a[4][4], b[4][2];
            #pragma unroll
            for (int i = 0; i < 4; i++)
                *reinterpret_cast<uint4*>(a[i]) =
                    *reinterpret_cast<const uint4*>(&Af[buf][(wm << 2) + i][kt][lane][0]);
            #pragma unroll
            for (int j = 0; j < 4; j++)
                *reinterpret_cast<uint2*>(b[j]) =
                    *reinterpret_cast<const uint2*>(&Bf[buf][kt][(wn << 2) + j][lane][0]);
            #pragma unroll
            for (int i = 0; i < 4; i++)
                #pragma unroll
                for (int j = 0; j < 4; j++)
                    asm volatile(
                        "mma.sync.aligned.m16n8k16.row.col.f32.bf16.bf16.f32 "
                        "{%0,%1,%2,%3}, {%4,%5,%6,%7}, {%8,%9}, {%0,%1,%2,%3};"
                        : "+f"(acc[i][j][0]), "+f"(acc[i][j][1]),
                          "+f"(acc[i][j][2]), "+f"(acc[i][j][3])
                        : "r"(a[i][0]), "r"(a[i][1]), "r"(a[i][2]), "r"(a[i][3]),
                          "r"(b[j][0]), "r"(b[j][1]));
        }
    };

    LDG(0);
    STS(0);
    __syncthreads();
    #pragma unroll 1
    for (int s = 0; s < 12; s++) {
        if (s < 11) LDG(s + 1);
        COMPUTE(s & 1);
        if (s < 11) {
            STS((s + 1) & 1);
            __syncthreads();
        }
    }

    // epilogue: add bias, store fp16 pairs
    int g = lane >> 2, tg = lane & 3;
    #pragma unroll
    for (int i = 0; i < 4; i++) {
        int r0 = bm + (wm << 6) + (i << 4) + g;
        #pragma unroll
        for (int j = 0; j < 4; j++) {
            int col = bn + (wn << 5) + (j << 3) + (tg << 1);
            float b0 = bias[col], b1 = bias[col + 1];
            if (r0 < M)
                *reinterpret_cast<__half2*>(C + (size_t)r0 * 4096 + col) =
                    __floats2half2_rn(acc[i][j][0] + b0, acc[i][j][1] + b1);
            if (r0 + 8 < M)
                *reinterpret_cast<__half2*>(C + (size_t)(r0 + 8) * 4096 + col) =
                    __floats2half2_rn(acc[i][j][2] + b0, acc[i][j][3] + b1);
        }
    }
}

// ---------------- per-edge message: msg[e]=feat[src[e]]@ew[e]; atomic agg ----
__global__ void k_msg(const int* __restrict__ ei, int E) {
    __shared__ float f_sh[4][DIM];
    int t = threadIdx.x;
    int eg = t >> 6, o = t & 63;
    int e = blockIdx.x * 4 + eg;
    if (e < E) {
        int src = ei[e];
        f_sh[eg][o] = g_h[(size_t)src * DIM + o];
    }
    __syncthreads();
    if (e >= E) return;
    const __half* ew = &g_ew16[(size_t)e * 4096 + o];
    const float* f = f_sh[eg];
    float acc = 0.f;
    #pragma unroll
    for (int i = 0; i < DIM; i++) acc = fmaf(f[i], __half2float(ew[(size_t)i * DIM]), acc);
    int dst = ei[E + e];
    atomicAdd(&g_agg[(size_t)dst * DIM + o], acc);
}

// ---------------- fused GRU: m=relu(agg*inv+b); h=GRU(m,h) -------------------
__global__ void k_gru_fused(const float* __restrict__ bih, const float* __restrict__ bhh,
                            const float* __restrict__ conv_b, int N) {
    extern __shared__ float sw[];            // 128*192 weights + 8*128 node bufs
    float* nb = sw + 128 * 192;
    for (int i = threadIdx.x; i < 128 * 192; i += 256) sw[i] = g_gruw[i];
    __syncthreads();
    int warp = threadIdx.x >> 5, lane = threadIdx.x & 31;
    float* in = nb + warp * 128;
    for (int n = blockIdx.x * 8 + warp; n < N; n += gridDim.x * 8) {
        float inv = g_invdeg[n];
        #pragma unroll
        for (int j = lane; j < 64; j += 32) {
            in[j] = fmaxf(fmaf(g_agg[n * 64 + j], inv, conv_b[j]), 0.f);
            in[64 + j] = g_h[n * 64 + j];
        }
        __syncwarp();
        float accrz[4];
        #pragma unroll
        for (int c = 0; c < 4; c++) {
            int g = lane + 32 * c;
            float a = bih[g] + bhh[g];
            #pragma unroll 16
            for (int k = 0; k < 128; k++) a = fmaf(in[k], sw[k * 192 + g], a);
            accrz[c] = a;
        }
        float ni[2], nh[2];
        #pragma unroll
        for (int c = 0; c < 2; c++) {
            int g = 128 + lane + 32 * c;
            float ai = bih[g], ah = bhh[g];
            #pragma unroll 16
            for (int k = 0; k < 64; k++) ai = fmaf(in[k], sw[k * 192 + g], ai);
            #pragma unroll 16
            for (int k = 64; k < 128; k++) ah = fmaf(in[k], sw[k * 192 + g], ah);
            ni[c] = ai; nh[c] = ah;
        }
        #pragma unroll
        for (int c = 0; c < 2; c++) {
            int d = lane + 32 * c;
            float r = sigf(accrz[c]);
            float z = sigf(accrz[2 + c]);
            float nn = tanhf(fmaf(r, nh[c], ni[c]));
            float hold = in[64 + d];
            g_h[n * 64 + d] = fmaf(z, hold - nn, nn);
        }
        __syncwarp();
    }
}

// ---------------- graph segment offsets --------------------------------------
__global__ void k_seg_zero(int B) {
    int b = threadIdx.x;
    if (b < B) { g_start[b] = 0x7fffffff; g_cnt[b] = 0; }
}
__global__ void k_seg_scan(const int* __restrict__ gidx, int N) {
    int n = blockIdx.x * blockDim.x + threadIdx.x;
    if (n >= N) return;
    int g = gidx[n];
    atomicMin(&g_start[g], n);
    atomicAdd(&g_cnt[g], 1);
}

// ---------------- fused Set2Set (3 steps) + FC head: one block per graph -----
__global__ void k_s2s_all(const float* __restrict__ bih, const float* __restrict__ bhh,
                          const float* __restrict__ fc1_w, const float* __restrict__ fc1_b,
                          const float* __restrict__ fc2_w, const float* __restrict__ fc2_b,
                          float* __restrict__ out) {
    int b = blockIdx.x, t = threadIdx.x;    // 256 threads
    __shared__ float q_sh[128], h_sh[64], lc_sh[64], gates[256], red[256], rpart[4][64];
    if (t < 128) q_sh[t] = 0.f;
    if (t < 64) { h_sh[t] = 0.f; lc_sh[t] = 0.f; }
    int s = g_start[b], c = g_cnt[b];
    if (s == 0x7fffffff) s = 0;
    __syncthreads();
    for (int step = 0; step < 3; step++) {
        float acc = bih[t] + bhh[t];
        #pragma unroll 8
        for (int k = 0; k < 128; k++) acc = fmaf(q_sh[k], g_s2s_wihT[k * 256 + t], acc);
        #pragma unroll 8
        for (int k = 0; k < 64; k++) acc = fmaf(h_sh[k], g_s2s_whhT[k * 256 + t], acc);
        gates[t] = acc;
        __syncthreads();
        if (t < 64) {
            float ig = sigf(gates[t]), fg = sigf(gates[64 + t]);
            float gg = tanhf(gates[128 + t]), og = sigf(gates[192 + t]);
            float cc = fmaf(fg, lc_sh[t], ig * gg);
            lc_sh[t] = cc;
            h_sh[t] = og * tanhf(cc);
        }
        __syncthreads();
        float lmax = -CUDART_INF_F;
        for (int n = s + t; n < s + c; n += 256) {
            const float* hp = &g_h[(size_t)n * DIM];
            float d = 0.f;
            #pragma unroll 8
            for (int k = 0; k < DIM; k++) d = fmaf(hp[k], h_sh[k], d);
            g_e[n] = d;
            lmax = fmaxf(lmax, d);
        }
        red[t] = lmax;
        __syncthreads();
        for (int off = 128; off > 0; off >>= 1) {
            if (t < off) red[t] = fmaxf(red[t], red[t + off]);
            __syncthreads();
        }
        float emax = red[0];
        __syncthreads();
        float lsum = 0.f;
        for (int n = s + t; n < s + c; n += 256) lsum += expf(g_e[n] - emax);
        red[t] = lsum;
        __syncthreads();
        for (int off = 128; off > 0; off >>= 1) {
            if (t < off) red[t] += red[t + off];
            __syncthreads();
        }
        float inv = red[0] > 0.f ? 1.f / red[0] : 0.f;
        __syncthreads();
        int d = t & 63, sub = t >> 6;
        float acc2 = 0.f;
        for (int n = s + sub; n < s + c; n += 4)
            acc2 = fmaf(expf(g_e[n] - emax), g_h[(size_t)n * DIM + d], acc2);
        rpart[sub][d] = acc2;
        __syncthreads();
        if (t < 64) {
            q_sh[64 + t] = (rpart[0][t] + rpart[1][t] + rpart[2][t] + rpart[3][t]) * inv;
            q_sh[t] = h_sh[t];
        }
        __syncthreads();
    }
    if (t < 64) {
        float acc = fc1_b[t];
        #pragma unroll 8
        for (int k = 0; k < 128; k++) acc = fmaf(q_sh[k], fc1_w[k * DIM + t], acc);
        red[t] = fmaxf(acc, 0.f) * fc2_w[t];
    }
    __syncthreads();
    for (int off = 32; off > 0; off >>= 1) {
        if (t < off) red[t] += red[t + off];
        __syncthreads();
    }
    if (t == 0) out[b] = red[0] + fc2_b[0];
}

// ---------------- launch -----------------------------------------------------
extern "C" void kernel_launch(void* const* d_in, const int* in_sizes, int n_in,
                              void* d_out, int out_size) {
    const int N = in_sizes[0] / 30;
    const int E = in_sizes[1] / 11;
    const int B = out_size;

    const float* nf   = (const float*)d_in[0];
    const float* ef   = (const float*)d_in[1];
    const int*   ei   = (const int*)d_in[2];
    const int*   gidx = (const int*)d_in[3];
    int wb = (in_sizes[4] == 1) ? 5 : 4;
    const float* lin0_w  = (const float*)d_in[wb + 0];
    const float* lin0_b  = (const float*)d_in[wb + 1];
    const float* enn_w1  = (const float*)d_in[wb + 2];
    const float* enn_b1  = (const float*)d_in[wb + 3];
    const float* enn_w2  = (const float*)d_in[wb + 4];
    const float* enn_b2  = (const float*)d_in[wb + 5];
    const float* conv_b  = (const float*)d_in[wb + 6];
    const float* gru_wih = (const float*)d_in[wb + 7];
    const float* gru_whh = (const float*)d_in[wb + 8];
    const float* gru_bih = (const float*)d_in[wb + 9];
    const float* gru_bhh = (const float*)d_in[wb + 10];
    const float* s2s_wih = (const float*)d_in[wb + 11];
    const float* s2s_whh = (const float*)d_in[wb + 12];
    const float* s2s_bih = (const float*)d_in[wb + 13];
    const float* s2s_bhh = (const float*)d_in[wb + 14];
    const float* fc1_w   = (const float*)d_in[wb + 15];
    const float* fc1_b   = (const float*)d_in[wb + 16];
    const float* fc2_w   = (const float*)d_in[wb + 17];
    const float* fc2_b   = (const float*)d_in[wb + 18];
    float* out = (float*)d_out;

    float *p_swihT, *p_swhhT, *p_agg;
    unsigned *p_ap, *p_bp;
    __half *p_ew;
    cudaGetSymbolAddress((void**)&p_swihT, g_s2s_wihT);
    cudaGetSymbolAddress((void**)&p_swhhT, g_s2s_whhT);
    cudaGetSymbolAddress((void**)&p_ap, g_apack);
    cudaGetSymbolAddress((void**)&p_bp, g_bpack);
    cudaGetSymbolAddress((void**)&p_ew, g_ew16);
    cudaGetSymbolAddress((void**)&p_agg, g_agg);
    int* p_deg; cudaGetSymbolAddress((void**)&p_deg, g_deg);

    cudaFuncSetAttribute(k_gru_fused, cudaFuncAttributeMaxDynamicSharedMemorySize, 102400);

    // Launches 1-3 prereqs; launch 4 = big GEMM (ncu profiles the 4th launch)
    k_enn1<<<(E * 64 + 255) / 256, 256>>>(ef, enn_w1, enn_b1, E);
    k_prep_b<<<(192 * 4096 + 255) / 256, 256>>>(enn_w2);
    k_lin0<<<(N * DIM + 255) / 256, 256>>>(nf, lin0_w, lin0_b, N);
    {
        dim3 grid(4096 / 128, (E + 127) / 128);
        k_gemm_bf16<<<grid, 256>>>(p_ap, p_bp, enn_b2, p_ew, E);
    }

    // degrees + weight preps
    k_prep_gru<<<(128 * 192 + 255) / 256, 256>>>(gru_wih, gru_whh);
    k_zero_i<<<(N + 255) / 256, 256>>>(p_deg, N);
    k_count<<<(E + 255) / 256, 256>>>(ei, E);
    k_invdeg<<<(N + 255) / 256, 256>>>(N);
    k_transpose<<<(256 * 128 + 255) / 256, 256>>>(p_swihT, s2s_wih, 256, 128);
    k_transpose<<<(256 * 64 + 255) / 256, 256>>>(p_swhhT, s2s_whh, 256, 64);

    // 3 message-passing + GRU iterations
    for (int it = 0; it < 3; it++) {
        k_zero_f<<<(N * DIM + 255) / 256, 256>>>(p_agg, N * DIM);
        k_msg<<<(E + 3) / 4, 256>>>(ei, E);
        k_gru_fused<<<148, 256, 102400>>>(gru_bih, gru_bhh, conv_b, N);
    }

    // Set2Set + FC head
    k_seg_zero<<<1, 128>>>(B);
    k_seg_scan<<<(N + 255) / 256, 256>>>(gidx, N);
    k_s2s_all<<<B, 256>>>(s2s_bih, s2s_bhh, fc1_w, fc1_b, fc2_w, fc2_b, out);
}

// round 8
// speedup vs baseline: 1.7432x; 1.0460x over previous
#include <cuda_runtime.h>
#include <cuda_bf16.h>
#include <cuda_fp16.h>
#include <cstdint>
#include <math_constants.h>

// ---------------- problem-size capacities (fixed by the dataset) -------------
#define NMAX 20000
#define EMAX 30000
#define BMAX 128
#define DIM  64

// ---------------- device scratch (static: no allocations allowed) ------------
__device__ __align__(256) float g_h[NMAX * DIM];
__device__ __align__(256) float g_agg[NMAX * DIM];
// A* pre-packed fragment order: [m16][16 k16][lane][reg]; k16 0-7 = a0, 8-15 = a1
__device__ __align__(256) unsigned g_apack[(size_t)1888 * 16 * 128];
// B* pre-packed fragment order: [16 k16][512 n8][lane][reg]; k16 0-7 = b0, 8-15 = b1
__device__ __align__(256) unsigned g_bpack[(size_t)16 * 512 * 64];
__device__ __align__(256) __half g_ew16[(size_t)EMAX * 4096];   // per-edge 64x64 (fp16)
__device__ int   g_deg[NMAX];
__device__ float g_invdeg[NMAX];
__device__ __align__(256) float g_gruw[128 * 192];
__device__ __align__(256) float g_s2s_wihT[128 * 256];
__device__ __align__(256) float g_s2s_whhT[DIM * 256];
__device__ float g_e[NMAX];
__device__ int   g_start[BMAX];
__device__ int   g_cnt[BMAX];

__device__ __forceinline__ float sigf(float x) { return 1.f / (1.f + expf(-x)); }
__device__ __forceinline__ unsigned bfpack(float lo, float hi) {
    __nv_bfloat16 l = __float2bfloat16(lo), h = __float2bfloat16(hi);
    return (unsigned)__bfloat16_as_ushort(l) | ((unsigned)__bfloat16_as_ushort(h) << 16);
}

// ---------------- small utility kernels --------------------------------------
__global__ void k_zero_i(int* p, int n) {
    int i = blockIdx.x * blockDim.x + threadIdx.x;
    if (i < n) p[i] = 0;
}
__global__ void k_transpose(float* dst, const float* __restrict__ src, int G, int K) {
    int idx = blockIdx.x * blockDim.x + threadIdx.x;
    if (idx >= G * K) return;
    int g = idx / K, k = idx % K;
    dst[k * G + g] = src[idx];
}
__global__ void k_prep_gru(const float* __restrict__ wih, const float* __restrict__ whh) {
    int idx = blockIdx.x * blockDim.x + threadIdx.x;
    if (idx >= 128 * 192) return;
    int k = idx / 192, g = idx % 192;
    g_gruw[idx] = (k < 64) ? wih[g * 64 + k] : whh[g * 64 + (k - 64)];
}

// ---- combined prep: ENN hidden -> A* fragments, and W2 -> B* fragments ------
__global__ void k_prep_all(const float* __restrict__ ef, const float* __restrict__ w1,
                           const float* __restrict__ b1, const float* __restrict__ w2,
                           int E) {
    int idx = blockIdx.x * blockDim.x + threadIdx.x;
    int na = E * 64;
    if (idx < na) {
        // ENN hidden: a = relu(ef@W1+b1), one thread = one (edge, col-pair)
        int e = idx >> 6, jp = idx & 63;
        int j0 = jp << 1;
        float f[11];
        #pragma unroll
        for (int k = 0; k < 11; k++) f[k] = ef[e * 11 + k];
        float a = b1[j0], b = b1[j0 + 1];
        #pragma unroll
        for (int k = 0; k < 11; k++) {
            a = fmaf(f[k], w1[k * 128 + j0], a);
            b = fmaf(f[k], w1[k * 128 + j0 + 1], b);
        }
        a = fmaxf(a, 0.f);
        b = fmaxf(b, 0.f);
        float a0 = __bfloat162float(__float2bfloat16(a));
        float b0 = __bfloat162float(__float2bfloat16(b));
        unsigned p0 = bfpack(a, b);
        unsigned p1 = bfpack(a - a0, b - b0);
        int m16 = e >> 4, r16 = e & 15;
        int k8 = j0 & 15;
        int lane = ((r16 & 7) << 2) | ((k8 >> 1) & 3);
        int reg = (r16 >> 3) | (((k8 >> 3) & 1) << 1);
        size_t base = ((size_t)m16 * 16 + (j0 >> 4)) * 128 + lane * 4 + reg;
        g_apack[base] = p0;                       // a0 region (k16 0..7)
        g_apack[base + (size_t)8 * 128] = p1;     // a1 region (k16 8..15)
    } else {
        int idx2 = idx - na;
        if (idx2 >= 128 * 4096) return;
        // B*: [b0;b1], K*=256; one thread = one (K*-pair, col)
        int kp = idx2 >> 12, n = idx2 & 4095;
        int Ks = kp << 1;                // 0..254
        int region = Ks >> 7;            // 0 -> b0, 1 -> b1
        int k = Ks & 127;
        float wa = w2[k * 4096 + n], wb = w2[(k + 1) * 4096 + n];
        float va, vb;
        if (region == 1) {
            va = wa - __bfloat162float(__float2bfloat16(wa));
            vb = wb - __bfloat162float(__float2bfloat16(wb));
        } else {
            va = wa; vb = wb;
        }
        unsigned u = bfpack(va, vb);
        int k16 = Ks >> 4, k8 = Ks & 15; // k16 0..7 (b0), 8..15 (b1)
        int lane = ((n & 7) << 2) | ((k8 >> 1) & 3);
        int reg = (k8 >> 3) & 1;
        g_bpack[((k16 * 512 + (n >> 3)) * 32 + lane) * 2 + reg] = u;
    }
}

// ---------------- lin0: h = relu(nf @ W + b); also zero agg ------------------
__global__ void k_lin0(const float* __restrict__ nf, const float* __restrict__ w,
                       const float* __restrict__ b, int N) {
    int idx = blockIdx.x * blockDim.x + threadIdx.x;
    if (idx >= N * DIM) return;
    int n = idx >> 6, d = idx & 63;
    float acc = b[d];
    #pragma unroll
    for (int k = 0; k < 30; k++) acc = fmaf(nf[n * 30 + k], w[k * DIM + d], acc);
    g_h[idx] = fmaxf(acc, 0.f);
    g_agg[idx] = 0.f;
}

// ---------------- degrees ----------------------------------------------------
__global__ void k_count(const int* __restrict__ ei, int E) {
    int e = blockIdx.x * blockDim.x + threadIdx.x;
    if (e < E) atomicAdd(&g_deg[ei[E + e]], 1);
}
__global__ void k_invdeg(int N) {
    int n = blockIdx.x * blockDim.x + threadIdx.x;
    if (n < N) g_invdeg[n] = 1.f / fmaxf((float)g_deg[n], 1.f);
}

// ---------------- bf16 GEMM, bf16x3 via 3 passes over shared staged tiles ----
// A* [m16][16][lane][reg]: k16 0-7 = a0 cols, 8-15 = a1. B* same split.
// C = a0b0 + a0b1 + a1b0 + bias, fp16 out. 8 stages; per stage: 48 mma.
__global__ void __launch_bounds__(256) k_gemm_bf16(
        const unsigned* __restrict__ Ap, const unsigned* __restrict__ Bp,
        const float* __restrict__ bias, __half* __restrict__ C, int M) {
    __shared__ __align__(16) unsigned Af[2][2][8][32][4];  // [buf][part][mt][lane][reg]
    __shared__ __align__(16) unsigned Bf[2][2][16][32][2]; // [buf][part][nt][lane][reg]
    const int tid = threadIdx.x;
    const int lane = tid & 31, warp = tid >> 5;
    const int wm = warp >> 2, wn = warp & 3;
    const int bm = blockIdx.y << 7, bn = blockIdx.x << 7;
    const uint4* Ap4 = reinterpret_cast<const uint4*>(Ap);
    const uint4* Bp4 = reinterpret_cast<const uint4*>(Bp);

    float acc[4][4][4];
    #pragma unroll
    for (int i = 0; i < 4; i++)
        #pragma unroll
        for (int j = 0; j < 4; j++)
            #pragma unroll
            for (int c = 0; c < 4; c++) acc[i][j][c] = 0.f;

    uint4 ra[2], rb[2];

    auto LDG = [&](int s) {
        #pragma unroll
        for (int l = 0; l < 2; l++) {
            int id = tid + (l << 8);                    // 0..511
            {   // A: part = id>>8, mt = (id>>5)&7, lane = id&31
                int la = id & 31, mt = (id >> 5) & 7, part = id >> 8;
                ra[l] = Ap4[(((size_t)((bm >> 4) + mt)) * 16 + (s + part * 8)) * 32 + la];
            }
            {   // B: part = id>>8, nt = (id>>4)&15, quad = id&15
                int quad = id & 15, nt = (id >> 4) & 15, part = id >> 8;
                rb[l] = Bp4[((size_t)(s + part * 8) * 512 + (bn >> 3) + nt) * 16 + quad];
            }
        }
    };
    auto STS = [&](int buf) {
        #pragma unroll
        for (int l = 0; l < 2; l++) {
            int id = tid + (l << 8);
            {
                int la = id & 31, mt = (id >> 5) & 7, part = id >> 8;
                *reinterpret_cast<uint4*>(&Af[buf][part][mt][la][0]) = ra[l];
            }
            {
                int quad = id & 15, nt = (id >> 4) & 15, part = id >> 8;
                *reinterpret_cast<uint4*>(&Bf[buf][part][nt][quad * 2][0]) = rb[l];
            }
        }
    };
    auto COMPUTE = [&](int buf) {
        unsigned a[4][4], b0[4][2], b1[4][2];
        #pragma unroll
        for (int j = 0; j < 4; j++) {
            *reinterpret_cast<uint2*>(b0[j]) =
                *reinterpret_cast<const uint2*>(&Bf[buf][0][(wn << 2) + j][lane][0]);
            *reinterpret_cast<uint2*>(b1[j]) =
                *reinterpret_cast<const uint2*>(&Bf[buf][1][(wn << 2) + j][lane][0]);
        }
        // pass 1+2: a0*b0, a0*b1
        #pragma unroll
        for (int i = 0; i < 4; i++)
            *reinterpret_cast<uint4*>(a[i]) =
                *reinterpret_cast<const uint4*>(&Af[buf][0][(wm << 2) + i][lane][0]);
        #pragma unroll
        for (int i = 0; i < 4; i++)
            #pragma unroll
            for (int j = 0; j < 4; j++)
                asm volatile(
                    "mma.sync.aligned.m16n8k16.row.col.f32.bf16.bf16.f32 "
                    "{%0,%1,%2,%3}, {%4,%5,%6,%7}, {%8,%9}, {%0,%1,%2,%3};"
                    : "+f"(acc[i][j][0]), "+f"(acc[i][j][1]),
                      "+f"(acc[i][j][2]), "+f"(acc[i][j][3])
                    : "r"(a[i][0]), "r"(a[i][1]), "r"(a[i][2]), "r"(a[i][3]),
                      "r"(b0[j][0]), "r"(b0[j][1]));
        #pragma unroll
        for (int i = 0; i < 4; i++)
            #pragma unroll
            for (int j = 0; j < 4; j++)
                asm volatile(
                    "mma.sync.aligned.m16n8k16.row.col.f32.bf16.bf16.f32 "
                    "{%0,%1,%2,%3}, {%4,%5,%6,%7}, {%8,%9}, {%0,%1,%2,%3};"
                    : "+f"(acc[i][j][0]), "+f"(acc[i][j][1]),
                      "+f"(acc[i][j][2]), "+f"(acc[i][j][3])
                    : "r"(a[i][0]), "r"(a[i][1]), "r"(a[i][2]), "r"(a[i][3]),
                      "r"(b1[j][0]), "r"(b1[j][1]));
        // pass 3: a1*b0
        #pragma unroll
        for (int i = 0; i < 4; i++)
            *reinterpret_cast<uint4*>(a[i]) =
                *reinterpret_cast<const uint4*>(&Af[buf][1][(wm << 2) + i][lane][0]);
        #pragma unroll
        for (int i = 0; i < 4; i++)
            #pragma unroll
            for (int j = 0; j < 4; j++)
                asm volatile(
                    "mma.sync.aligned.m16n8k16.row.col.f32.bf16.bf16.f32 "
                    "{%0,%1,%2,%3}, {%4,%5,%6,%7}, {%8,%9}, {%0,%1,%2,%3};"
                    : "+f"(acc[i][j][0]), "+f"(acc[i][j][1]),
                      "+f"(acc[i][j][2]), "+f"(acc[i][j][3])
                    : "r"(a[i][0]), "r"(a[i][1]), "r"(a[i][2]), "r"(a[i][3]),
                      "r"(b0[j][0]), "r"(b0[j][1]));
    };

    LDG(0);
    STS(0);
    __syncthreads();
    #pragma unroll 1
    for (int s = 0; s < 8; s++) {
        if (s < 7) LDG(s + 1);
        COMPUTE(s & 1);
        if (s < 7) {
            STS((s + 1) & 1);
            __syncthreads();
        }
    }

    // epilogue: add bias, store fp16 pairs
    int g = lane >> 2, tg = lane & 3;
    #pragma unroll
    for (int i = 0; i < 4; i++) {
        int r0 = bm + (wm << 6) + (i << 4) + g;
        #pragma unroll
        for (int j = 0; j < 4; j++) {
            int col = bn + (wn << 5) + (j << 3) + (tg << 1);
            float b0 = bias[col], b1 = bias[col + 1];
            if (r0 < M)
                *reinterpret_cast<__half2*>(C + (size_t)r0 * 4096 + col) =
                    __floats2half2_rn(acc[i][j][0] + b0, acc[i][j][1] + b1);
            if (r0 + 8 < M)
                *reinterpret_cast<__half2*>(C + (size_t)(r0 + 8) * 4096 + col) =
                    __floats2half2_rn(acc[i][j][2] + b0, acc[i][j][3] + b1);
        }
    }
}

// ---------------- per-edge message: msg[e]=feat[src[e]]@ew[e]; atomic agg ----
__global__ void k_msg(const int* __restrict__ ei, int E) {
    __shared__ float f_sh[4][DIM];
    int t = threadIdx.x;
    int eg = t >> 6, o = t & 63;
    int e = blockIdx.x * 4 + eg;
    if (e < E) {
        int src = ei[e];
        f_sh[eg][o] = g_h[(size_t)src * DIM + o];
    }
    __syncthreads();
    if (e >= E) return;
    const __half* ew = &g_ew16[(size_t)e * 4096 + o];
    const float* f = f_sh[eg];
    float acc = 0.f;
    #pragma unroll
    for (int i = 0; i < DIM; i++) acc = fmaf(f[i], __half2float(ew[(size_t)i * DIM]), acc);
    int dst = ei[E + e];
    atomicAdd(&g_agg[(size_t)dst * DIM + o], acc);
}

// ---------------- fused GRU: m=relu(agg*inv+b); h=GRU(m,h); re-zero agg ------
__global__ void k_gru_fused(const float* __restrict__ bih, const float* __restrict__ bhh,
                            const float* __restrict__ conv_b, int N) {
    extern __shared__ float sw[];            // 128*192 weights + 8*128 node bufs
    float* nb = sw + 128 * 192;
    for (int i = threadIdx.x; i < 128 * 192; i += 256) sw[i] = g_gruw[i];
    __syncthreads();
    int warp = threadIdx.x >> 5, lane = threadIdx.x & 31;
    float* in = nb + warp * 128;
    for (int n = blockIdx.x * 8 + warp; n < N; n += gridDim.x * 8) {
        float inv = g_invdeg[n];
        #pragma unroll
        for (int j = lane; j < 64; j += 32) {
            in[j] = fmaxf(fmaf(g_agg[n * 64 + j], inv, conv_b[j]), 0.f);
            g_agg[n * 64 + j] = 0.f;         // re-zero for next msg iteration
            in[64 + j] = g_h[n * 64 + j];
        }
        __syncwarp();
        float accrz[4];
        #pragma unroll
        for (int c = 0; c < 4; c++) {
            int g = lane + 32 * c;
            float x = bih[g] + bhh[g], y = 0.f;
            #pragma unroll 16
            for (int k = 0; k < 64; k++) x = fmaf(in[k], sw[k * 192 + g], x);
            #pragma unroll 16
            for (int k = 64; k < 128; k++) y = fmaf(in[k], sw[k * 192 + g], y);
            accrz[c] = x + y;
        }
        float ni[2], nh[2];
        #pragma unroll
        for (int c = 0; c < 2; c++) {
            int g = 128 + lane + 32 * c;
            float ai = bih[g], ah = bhh[g];
            #pragma unroll 16
            for (int k = 0; k < 64; k++) ai = fmaf(in[k], sw[k * 192 + g], ai);
            #pragma unroll 16
            for (int k = 64; k < 128; k++) ah = fmaf(in[k], sw[k * 192 + g], ah);
            ni[c] = ai; nh[c] = ah;
        }
        #pragma unroll
        for (int c = 0; c < 2; c++) {
            int d = lane + 32 * c;
            float r = sigf(accrz[c]);
            float z = sigf(accrz[2 + c]);
            float nn = tanhf(fmaf(r, nh[c], ni[c]));
            float hold = in[64 + d];
            g_h[n * 64 + d] = fmaf(z, hold - nn, nn);
        }
        __syncwarp();
    }
}

// ---------------- graph segment offsets --------------------------------------
__global__ void k_seg_zero(int B) {
    int b = threadIdx.x;
    if (b < B) { g_start[b] = 0x7fffffff; g_cnt[b] = 0; }
}
__global__ void k_seg_scan(const int* __restrict__ gidx, int N) {
    int n = blockIdx.x * blockDim.x + threadIdx.x;
    if (n >= N) return;
    int g = gidx[n];
    atomicMin(&g_start[g], n);
    atomicAdd(&g_cnt[g], 1);
}

// ---------------- fused Set2Set (3 steps) + FC head: one block per graph -----
__global__ void k_s2s_all(const float* __restrict__ bih, const float* __restrict__ bhh,
                          const float* __restrict__ fc1_w, const float* __restrict__ fc1_b,
                          const float* __restrict__ fc2_w, const float* __restrict__ fc2_b,
                          float* __restrict__ out) {
    int b = blockIdx.x, t = threadIdx.x;    // 256 threads
    __shared__ float q_sh[128], h_sh[64], lc_sh[64], gates[256], red[256], rpart[4][64];
    if (t < 128) q_sh[t] = 0.f;
    if (t < 64) { h_sh[t] = 0.f; lc_sh[t] = 0.f; }
    int s = g_start[b], c = g_cnt[b];
    if (s == 0x7fffffff) s = 0;
    __syncthreads();
    for (int step = 0; step < 3; step++) {
        float acc = bih[t] + bhh[t];
        #pragma unroll 8
        for (int k = 0; k < 128; k++) acc = fmaf(q_sh[k], g_s2s_wihT[k * 256 + t], acc);
        #pragma unroll 8
        for (int k = 0; k < 64; k++) acc = fmaf(h_sh[k], g_s2s_whhT[k * 256 + t], acc);
        gates[t] = acc;
        __syncthreads();
        if (t < 64) {
            float ig = sigf(gates[t]), fg = sigf(gates[64 + t]);
            float gg = tanhf(gates[128 + t]), og = sigf(gates[192 + t]);
            float cc = fmaf(fg, lc_sh[t], ig * gg);
            lc_sh[t] = cc;
            h_sh[t] = og * tanhf(cc);
        }
        __syncthreads();
        float lmax = -CUDART_INF_F;
        for (int n = s + t; n < s + c; n += 256) {
            const float* hp = &g_h[(size_t)n * DIM];
            float d = 0.f;
            #pragma unroll 8
            for (int k = 0; k < DIM; k++) d = fmaf(hp[k], h_sh[k], d);
            g_e[n] = d;
            lmax = fmaxf(lmax, d);
        }
        red[t] = lmax;
        __syncthreads();
        for (int off = 128; off > 0; off >>= 1) {
            if (t < off) red[t] = fmaxf(red[t], red[t + off]);
            __syncthreads();
        }
        float emax = red[0];
        __syncthreads();
        float lsum = 0.f;
        for (int n = s + t; n < s + c; n += 256) lsum += expf(g_e[n] - emax);
        red[t] = lsum;
        __syncthreads();
        for (int off = 128; off > 0; off >>= 1) {
            if (t < off) red[t] += red[t + off];
            __syncthreads();
        }
        float inv = red[0] > 0.f ? 1.f / red[0] : 0.f;
        __syncthreads();
        int d = t & 63, sub = t >> 6;
        float acc2 = 0.f;
        for (int n = s + sub; n < s + c; n += 4)
            acc2 = fmaf(expf(g_e[n] - emax), g_h[(size_t)n * DIM + d], acc2);
        rpart[sub][d] = acc2;
        __syncthreads();
        if (t < 64) {
            q_sh[64 + t] = (rpart[0][t] + rpart[1][t] + rpart[2][t] + rpart[3][t]) * inv;
            q_sh[t] = h_sh[t];
        }
        __syncthreads();
    }
    if (t < 64) {
        float acc = fc1_b[t];
        #pragma unroll 8
        for (int k = 0; k < 128; k++) acc = fmaf(q_sh[k], fc1_w[k * DIM + t], acc);
        red[t] = fmaxf(acc, 0.f) * fc2_w[t];
    }
    __syncthreads();
    for (int off = 32; off > 0; off >>= 1) {
        if (t < off) red[t] += red[t + off];
        __syncthreads();
    }
    if (t == 0) out[b] = red[0] + fc2_b[0];
}

// ---------------- launch -----------------------------------------------------
extern "C" void kernel_launch(void* const* d_in, const int* in_sizes, int n_in,
                              void* d_out, int out_size) {
    const int N = in_sizes[0] / 30;
    const int E = in_sizes[1] / 11;
    const int B = out_size;

    const float* nf   = (const float*)d_in[0];
    const float* ef   = (const float*)d_in[1];
    const int*   ei   = (const int*)d_in[2];
    const int*   gidx = (const int*)d_in[3];
    int wb = (in_sizes[4] == 1) ? 5 : 4;
    const float* lin0_w  = (const float*)d_in[wb + 0];
    const float* lin0_b  = (const float*)d_in[wb + 1];
    const float* enn_w1  = (const float*)d_in[wb + 2];
    const float* enn_b1  = (const float*)d_in[wb + 3];
    const float* enn_w2  = (const float*)d_in[wb + 4];
    const float* enn_b2  = (const float*)d_in[wb + 5];
    const float* conv_b  = (const float*)d_in[wb + 6];
    const float* gru_wih = (const float*)d_in[wb + 7];
    const float* gru_whh = (const float*)d_in[wb + 8];
    const float* gru_bih = (const float*)d_in[wb + 9];
    const float* gru_bhh = (const float*)d_in[wb + 10];
    const float* s2s_wih = (const float*)d_in[wb + 11];
    const float* s2s_whh = (const float*)d_in[wb + 12];
    const float* s2s_bih = (const float*)d_in[wb + 13];
    const float* s2s_bhh = (const float*)d_in[wb + 14];
    const float* fc1_w   = (const float*)d_in[wb + 15];
    const float* fc1_b   = (const float*)d_in[wb + 16];
    const float* fc2_w   = (const float*)d_in[wb + 17];
    const float* fc2_b   = (const float*)d_in[wb + 18];
    float* out = (float*)d_out;

    float *p_swihT, *p_swhhT;
    unsigned *p_ap, *p_bp;
    __half *p_ew;
    cudaGetSymbolAddress((void**)&p_swihT, g_s2s_wihT);
    cudaGetSymbolAddress((void**)&p_swhhT, g_s2s_whhT);
    cudaGetSymbolAddress((void**)&p_ap, g_apack);
    cudaGetSymbolAddress((void**)&p_bp, g_bpack);
    cudaGetSymbolAddress((void**)&p_ew, g_ew16);
    int* p_deg; cudaGetSymbolAddress((void**)&p_deg, g_deg);

    cudaFuncSetAttribute(k_gru_fused, cudaFuncAttributeMaxDynamicSharedMemorySize, 102400);

    // 1-3: prep + GEMM; launch 4 = k_msg (capture target this round)
    {
        int total = E * 64 + 128 * 4096;
        k_prep_all<<<(total + 255) / 256, 256>>>(ef, enn_w1, enn_b1, enn_w2, E);
    }
    k_lin0<<<(N * DIM + 255) / 256, 256>>>(nf, lin0_w, lin0_b, N);
    {
        dim3 grid(4096 / 128, (E + 127) / 128);
        k_gemm_bf16<<<grid, 256>>>(p_ap, p_bp, enn_b2, p_ew, E);
    }
    k_msg<<<(E + 3) / 4, 256>>>(ei, E);          // iteration 1 message pass

    // degrees + GRU weight prep (needed before first GRU)
    k_prep_gru<<<(128 * 192 + 255) / 256, 256>>>(gru_wih, gru_whh);
    k_zero_i<<<(N + 255) / 256, 256>>>(p_deg, N);
    k_count<<<(E + 255) / 256, 256>>>(ei, E);
    k_invdeg<<<(N + 255) / 256, 256>>>(N);

    k_gru_fused<<<148, 256, 102400>>>(gru_bih, gru_bhh, conv_b, N);   // iter 1
    for (int it = 1; it < 3; it++) {
        k_msg<<<(E + 3) / 4, 256>>>(ei, E);
        k_gru_fused<<<148, 256, 102400>>>(gru_bih, gru_bhh, conv_b, N);
    }

    // Set2Set + FC head
    k_transpose<<<(256 * 128 + 255) / 256, 256>>>(p_swihT, s2s_wih, 256, 128);
    k_transpose<<<(256 * 64 + 255) / 256, 256>>>(p_swhhT, s2s_whh, 256, 64);
    k_seg_zero<<<1, 128>>>(B);
    k_seg_scan<<<(N + 255) / 256, 256>>>(gidx, N);
    k_s2s_all<<<B, 256>>>(s2s_bih, s2s_bhh, fc1_w, fc1_b, fc2_w, fc2_b, out);
}

// round 10
// speedup vs baseline: 2.3427x; 1.3439x over previous
#include <cuda_runtime.h>
#include <cuda_bf16.h>
#include <cuda_fp16.h>
#include <cstdint>
#include <type_traits>
#include <math_constants.h>

// ---------------- problem-size capacities (fixed by the dataset) -------------
#define NMAX 20000
#define EMAX 30000
#define BMAX 128
#define DIM  64

// ---------------- device scratch (static: no allocations allowed) ------------
__device__ __align__(256) float g_h[NMAX * DIM];
__device__ __align__(256) float g_agg[NMAX * DIM];
// A* fragments: [m16][16 k16][lane][reg]; k16 0-7 = a0, 8-15 = a1
__device__ __align__(256) unsigned g_apack[(size_t)1888 * 16 * 128];
// B* fragments: [16 k16][512 n8][lane][reg]; k16 0-7 = b0, 8-15 = b1
__device__ __align__(256) unsigned g_bpack[(size_t)16 * 512 * 64];
// X* fragments for GRU GEMM: [1256 m16][16 k16][lane][reg]
__device__ __align__(256) unsigned g_xpack[(size_t)1256 * 16 * 128];
// W'' fragments for GRU GEMM: [16 k16][32 n8][lane][reg]
__device__ __align__(256) unsigned g_gpack[16 * 32 * 64];
__device__ __align__(256) float g_gbias[256];
__device__ __align__(256) float g_gates[(size_t)20096 * 256];
__device__ __align__(256) __half g_ew16[(size_t)EMAX * 4096];
__device__ int   g_deg[NMAX];
__device__ float g_invdeg[NMAX];
__device__ __align__(256) float g_s2s_wihT[128 * 256];
__device__ __align__(256) float g_s2s_whhT[DIM * 256];
__device__ float g_e[NMAX];
__device__ int   g_start[BMAX];
__device__ int   g_cnt[BMAX];

__device__ __forceinline__ float sigf(float x) { return 1.f / (1.f + expf(-x)); }
__device__ __forceinline__ unsigned bfpack(float lo, float hi) {
    __nv_bfloat16 l = __float2bfloat16(lo), h = __float2bfloat16(hi);
    return (unsigned)__bfloat16_as_ushort(l) | ((unsigned)__bfloat16_as_ushort(h) << 16);
}

// ---------------- small utility kernels --------------------------------------
__global__ void k_zero_i(int* p, int n) {
    int i = blockIdx.x * blockDim.x + threadIdx.x;
    if (i < n) p[i] = 0;
}
__global__ void k_transpose(float* dst, const float* __restrict__ src, int G, int K) {
    int idx = blockIdx.x * blockDim.x + threadIdx.x;
    if (idx >= G * K) return;
    int g = idx / K, k = idx % K;
    dst[k * G + g] = src[idx];
}

// ---- combined prep: ENN hidden -> A* fragments, and W2 -> B* fragments ------
__global__ void k_prep_all(const float* __restrict__ ef, const float* __restrict__ w1,
                           const float* __restrict__ b1, const float* __restrict__ w2,
                           int E) {
    int idx = blockIdx.x * blockDim.x + threadIdx.x;
    int na = E * 64;
    if (idx < na) {
        int e = idx >> 6, jp = idx & 63;
        int j0 = jp << 1;
        float f[11];
        #pragma unroll
        for (int k = 0; k < 11; k++) f[k] = ef[e * 11 + k];
        float a = b1[j0], b = b1[j0 + 1];
        #pragma unroll
        for (int k = 0; k < 11; k++) {
            a = fmaf(f[k], w1[k * 128 + j0], a);
            b = fmaf(f[k], w1[k * 128 + j0 + 1], b);
        }
        a = fmaxf(a, 0.f);
        b = fmaxf(b, 0.f);
        float a0 = __bfloat162float(__float2bfloat16(a));
        float b0 = __bfloat162float(__float2bfloat16(b));
        unsigned p0 = bfpack(a, b);
        unsigned p1 = bfpack(a - a0, b - b0);
        int m16 = e >> 4, r16 = e & 15;
        int k8 = j0 & 15;
        int lane = ((r16 & 7) << 2) | ((k8 >> 1) & 3);
        int reg = (r16 >> 3) | (((k8 >> 3) & 1) << 1);
        size_t base = ((size_t)m16 * 16 + (j0 >> 4)) * 128 + lane * 4 + reg;
        g_apack[base] = p0;
        g_apack[base + (size_t)8 * 128] = p1;
    } else {
        int idx2 = idx - na;
        if (idx2 >= 128 * 4096) return;
        int kp = idx2 >> 12, n = idx2 & 4095;
        int Ks = kp << 1;
        int region = Ks >> 7;
        int k = Ks & 127;
        float wa = w2[k * 4096 + n], wb = w2[(k + 1) * 4096 + n];
        float va, vb;
        if (region == 1) {
            va = wa - __bfloat162float(__float2bfloat16(wa));
            vb = wb - __bfloat162float(__float2bfloat16(wb));
        } else {
            va = wa; vb = wb;
        }
        unsigned u = bfpack(va, vb);
        int k16 = Ks >> 4, k8 = Ks & 15;
        int lane = ((n & 7) << 2) | ((k8 >> 1) & 3);
        int reg = (k8 >> 3) & 1;
        g_bpack[((k16 * 512 + (n >> 3)) * 32 + lane) * 2 + reg] = u;
    }
}

// ---- GRU stacked-weight prep: W''[128][256] + bias[256] ---------------------
// cols: 0-63 r_sum, 64-127 z_sum, 128-191 i_n, 192-255 h_n
// Enumerates logical K*=256 = [lo(128); residual(128)] like the B prep above.
__device__ __forceinline__ float gru_wfull(const float* wih, const float* whh, int k, int c) {
    if (c < 128) return (k < 64) ? wih[c * 64 + k] : whh[c * 64 + (k - 64)];
    if (c < 192) return (k < 64) ? wih[c * 64 + k] : 0.f;
    return (k < 64) ? 0.f : whh[(c - 64) * 64 + (k - 64)];
}
__global__ void k_prep_gruw(const float* __restrict__ wih, const float* __restrict__ whh,
                            const float* __restrict__ bih, const float* __restrict__ bhh) {
    int idx = blockIdx.x * blockDim.x + threadIdx.x;
    if (idx >= 128 * 256) return;
    int kp = idx >> 8, c = idx & 255;
    int Ks = kp << 1;
    int region = Ks >> 7;
    int k = Ks & 127;
    float wa = gru_wfull(wih, whh, k, c), wb = gru_wfull(wih, whh, k + 1, c);
    float va, vb;
    if (region == 1) {
        va = wa - __bfloat162float(__float2bfloat16(wa));
        vb = wb - __bfloat162float(__float2bfloat16(wb));
    } else {
        va = wa; vb = wb;
    }
    unsigned u = bfpack(va, vb);
    int k16 = Ks >> 4, k8 = Ks & 15;
    int lane = ((c & 7) << 2) | ((k8 >> 1) & 3);
    int reg = (k8 >> 3) & 1;
    g_gpack[((k16 * 32 + (c >> 3)) * 32 + lane) * 2 + reg] = u;
    if (kp == 0) {
        float bias;
        if (c < 128) bias = bih[c] + bhh[c];
        else if (c < 192) bias = bih[c];
        else bias = bhh[c - 64];
        g_gbias[c] = bias;
    }
}

// ---------------- lin0: h = relu(nf @ W + b); also zero agg ------------------
__global__ void k_lin0(const float* __restrict__ nf, const float* __restrict__ w,
                       const float* __restrict__ b, int N) {
    int idx = blockIdx.x * blockDim.x + threadIdx.x;
    if (idx >= N * DIM) return;
    int n = idx >> 6, d = idx & 63;
    float acc = b[d];
    #pragma unroll
    for (int k = 0; k < 30; k++) acc = fmaf(nf[n * 30 + k], w[k * DIM + d], acc);
    g_h[idx] = fmaxf(acc, 0.f);
    g_agg[idx] = 0.f;
}

// ---------------- degrees ----------------------------------------------------
__global__ void k_count(const int* __restrict__ ei, int E) {
    int e = blockIdx.x * blockDim.x + threadIdx.x;
    if (e < E) atomicAdd(&g_deg[ei[E + e]], 1);
}
__global__ void k_invdeg(int N) {
    int n = blockIdx.x * blockDim.x + threadIdx.x;
    if (n < N) g_invdeg[n] = 1.f / fmaxf((float)g_deg[n], 1.f);
}

// ---------------- templated fragment GEMM (bf16x3, 3 passes, 8 stages) -------
template <int N8TOT, typename OutT>
__global__ void __launch_bounds__(256) k_gemm_frag(
        const unsigned* __restrict__ Ap, const unsigned* __restrict__ Bp,
        const float* __restrict__ bias, OutT* __restrict__ C, int M) {
    constexpr int LDC = N8TOT * 8;
    __shared__ __align__(16) unsigned Af[2][2][8][32][4];
    __shared__ __align__(16) unsigned Bf[2][2][16][32][2];
    const int tid = threadIdx.x;
    const int lane = tid & 31, warp = tid >> 5;
    const int wm = warp >> 2, wn = warp & 3;
    const int bm = blockIdx.y << 7, bn = blockIdx.x << 7;
    const uint4* Ap4 = reinterpret_cast<const uint4*>(Ap);
    const uint4* Bp4 = reinterpret_cast<const uint4*>(Bp);

    float acc[4][4][4];
    #pragma unroll
    for (int i = 0; i < 4; i++)
        #pragma unroll
        for (int j = 0; j < 4; j++)
            #pragma unroll
            for (int c = 0; c < 4; c++) acc[i][j][c] = 0.f;

    uint4 ra[2], rb[2];

    auto LDG = [&](int s) {
        #pragma unroll
        for (int l = 0; l < 2; l++) {
            int id = tid + (l << 8);
            {
                int la = id & 31, mt = (id >> 5) & 7, part = id >> 8;
                ra[l] = Ap4[(((size_t)((bm >> 4) + mt)) * 16 + (s + part * 8)) * 32 + la];
            }
            {
                int quad = id & 15, nt = (id >> 4) & 15, part = id >> 8;
                rb[l] = Bp4[((size_t)(s + part * 8) * N8TOT + (bn >> 3) + nt) * 16 + quad];
            }
        }
    };
    auto STS = [&](int buf) {
        #pragma unroll
        for (int l = 0; l < 2; l++) {
            int id = tid + (l << 8);
            {
                int la = id & 31, mt = (id >> 5) & 7, part = id >> 8;
                *reinterpret_cast<uint4*>(&Af[buf][part][mt][la][0]) = ra[l];
            }
            {
                int quad = id & 15, nt = (id >> 4) & 15, part = id >> 8;
                *reinterpret_cast<uint4*>(&Bf[buf][part][nt][quad * 2][0]) = rb[l];
            }
        }
    };
    auto COMPUTE = [&](int buf) {
        unsigned a[4][4], b0[4][2], b1[4][2];
        #pragma unroll
        for (int j = 0; j < 4; j++) {
            *reinterpret_cast<uint2*>(b0[j]) =
                *reinterpret_cast<const uint2*>(&Bf[buf][0][(wn << 2) + j][lane][0]);
            *reinterpret_cast<uint2*>(b1[j]) =
                *reinterpret_cast<const uint2*>(&Bf[buf][1][(wn << 2) + j][lane][0]);
        }
        #pragma unroll
        for (int i = 0; i < 4; i++)
            *reinterpret_cast<uint4*>(a[i]) =
                *reinterpret_cast<const uint4*>(&Af[buf][0][(wm << 2) + i][lane][0]);
        #pragma unroll
        for (int i = 0; i < 4; i++)
            #pragma unroll
            for (int j = 0; j < 4; j++)
                asm volatile(
                    "mma.sync.aligned.m16n8k16.row.col.f32.bf16.bf16.f32 "
                    "{%0,%1,%2,%3}, {%4,%5,%6,%7}, {%8,%9}, {%0,%1,%2,%3};"
                    : "+f"(acc[i][j][0]), "+f"(acc[i][j][1]),
                      "+f"(acc[i][j][2]), "+f"(acc[i][j][3])
                    : "r"(a[i][0]), "r"(a[i][1]), "r"(a[i][2]), "r"(a[i][3]),
                      "r"(b0[j][0]), "r"(b0[j][1]));
        #pragma unroll
        for (int i = 0; i < 4; i++)
            #pragma unroll
            for (int j = 0; j < 4; j++)
                asm volatile(
                    "mma.sync.aligned.m16n8k16.row.col.f32.bf16.bf16.f32 "
                    "{%0,%1,%2,%3}, {%4,%5,%6,%7}, {%8,%9}, {%0,%1,%2,%3};"
                    : "+f"(acc[i][j][0]), "+f"(acc[i][j][1]),
                      "+f"(acc[i][j][2]), "+f"(acc[i][j][3])
                    : "r"(a[i][0]), "r"(a[i][1]), "r"(a[i][2]), "r"(a[i][3]),
                      "r"(b1[j][0]), "r"(b1[j][1]));
        #pragma unroll
        for (int i = 0; i < 4; i++)
            *reinterpret_cast<uint4*>(a[i]) =
                *reinterpret_cast<const uint4*>(&Af[buf][1][(wm << 2) + i][lane][0]);
        #pragma unroll
        for (int i = 0; i < 4; i++)
            #pragma unroll
            for (int j = 0; j < 4; j++)
                asm volatile(
                    "mma.sync.aligned.m16n8k16.row.col.f32.bf16.bf16.f32 "
                    "{%0,%1,%2,%3}, {%4,%5,%6,%7}, {%8,%9}, {%0,%1,%2,%3};"
                    : "+f"(acc[i][j][0]), "+f"(acc[i][j][1]),
                      "+f"(acc[i][j][2]), "+f"(acc[i][j][3])
                    : "r"(a[i][0]), "r"(a[i][1]), "r"(a[i][2]), "r"(a[i][3]),
                      "r"(b0[j][0]), "r"(b0[j][1]));
    };

    LDG(0);
    STS(0);
    __syncthreads();
    #pragma unroll 1
    for (int s = 0; s < 8; s++) {
        if (s < 7) LDG(s + 1);
        COMPUTE(s & 1);
        if (s < 7) {
            STS((s + 1) & 1);
            __syncthreads();
        }
    }

    int g = lane >> 2, tg = lane & 3;
    #pragma unroll
    for (int i = 0; i < 4; i++) {
        int r0 = bm + (wm << 6) + (i << 4) + g;
        #pragma unroll
        for (int j = 0; j < 4; j++) {
            int col = bn + (wn << 5) + (j << 3) + (tg << 1);
            float b0 = bias[col], b1 = bias[col + 1];
            float v0 = acc[i][j][0] + b0, v1 = acc[i][j][1] + b1;
            float v2 = acc[i][j][2] + b0, v3 = acc[i][j][3] + b1;
            if (r0 < M) {
                if constexpr (std::is_same<OutT, __half>::value)
                    *reinterpret_cast<__half2*>(C + (size_t)r0 * LDC + col) = __floats2half2_rn(v0, v1);
                else
                    *reinterpret_cast<float2*>(C + (size_t)r0 * LDC + col) = make_float2(v0, v1);
            }
            if (r0 + 8 < M) {
                if constexpr (std::is_same<OutT, __half>::value)
                    *reinterpret_cast<__half2*>(C + (size_t)(r0 + 8) * LDC + col) = __floats2half2_rn(v2, v3);
                else
                    *reinterpret_cast<float2*>(C + (size_t)(r0 + 8) * LDC + col) = make_float2(v2, v3);
            }
        }
    }
}

// ---------------- per-edge message: 32 thr/edge, half2 loads -----------------
__global__ void k_msg(const int* __restrict__ ei, int E) {
    __shared__ float f_sh[8][DIM];
    int t = threadIdx.x;
    int eg = t >> 5, tl = t & 31;
    int e = blockIdx.x * 8 + eg;
    if (e < E) {
        int src = ei[e];
        f_sh[eg][tl] = g_h[(size_t)src * DIM + tl];
        f_sh[eg][tl + 32] = g_h[(size_t)src * DIM + tl + 32];
    }
    __syncthreads();
    if (e >= E) return;
    const __half2* ew = reinterpret_cast<const __half2*>(g_ew16 + (size_t)e * 4096) + tl;
    const float* f = f_sh[eg];
    float acc0 = 0.f, acc1 = 0.f;
    #pragma unroll
    for (int i = 0; i < DIM; i++) {
        float2 w = __half22float2(ew[i * 32]);
        acc0 = fmaf(f[i], w.x, acc0);
        acc1 = fmaf(f[i], w.y, acc1);
    }
    int dst = ei[E + e];
    atomicAdd(&g_agg[(size_t)dst * DIM + 2 * tl], acc0);
    atomicAdd(&g_agg[(size_t)dst * DIM + 2 * tl + 1], acc1);
}

// ---------------- X* pack for GRU GEMM: X=[m|h] (128 cols = 64 pairs) --------
// FIXED from R9: enumerate 64 physical column-pairs per node (A-prep
// convention: lo to k16 0-7, residual to k16 8-15). R9's jp&127 wrote garbage
// over the residual region AND read out-of-row g_h.
__global__ void k_xpack(const float* __restrict__ conv_b, int N) {
    int idx = blockIdx.x * blockDim.x + threadIdx.x;
    if (idx >= N * 64) return;
    int n = idx >> 6, jp = idx & 63;
    int j0 = jp << 1;                    // 0..126, physical X column pair
    float a, b;
    if (j0 < 64) {
        float inv = g_invdeg[n];
        a = fmaxf(fmaf(g_agg[n * 64 + j0], inv, conv_b[j0]), 0.f);
        b = fmaxf(fmaf(g_agg[n * 64 + j0 + 1], inv, conv_b[j0 + 1]), 0.f);
        g_agg[n * 64 + j0] = 0.f;
        g_agg[n * 64 + j0 + 1] = 0.f;
    } else {
        a = g_h[n * 64 + (j0 - 64)];
        b = g_h[n * 64 + (j0 - 63)];
    }
    float a0 = __bfloat162float(__float2bfloat16(a));
    float b0 = __bfloat162float(__float2bfloat16(b));
    unsigned p0 = bfpack(a, b);
    unsigned p1 = bfpack(a - a0, b - b0);
    int m16 = n >> 4, r16 = n & 15;
    int k8 = j0 & 15;
    int lane = ((r16 & 7) << 2) | ((k8 >> 1) & 3);
    int reg = (r16 >> 3) | (((k8 >> 3) & 1) << 1);
    size_t base = ((size_t)m16 * 16 + (j0 >> 4)) * 128 + lane * 4 + reg;
    g_xpack[base] = p0;                      // lo -> k16 0..7
    g_xpack[base + (size_t)8 * 128] = p1;    // residual -> k16 8..15
}

// ---------------- GRU combine from stacked gates -----------------------------
__global__ void k_gru_combine(int N) {
    int idx = blockIdx.x * blockDim.x + threadIdx.x;
    if (idx >= N * DIM) return;
    int n = idx >> 6, d = idx & 63;
    const float* g = &g_gates[(size_t)n * 256];
    float r = sigf(g[d]);
    float z = sigf(g[64 + d]);
    float nn = tanhf(fmaf(r, g[192 + d], g[128 + d]));
    float hold = g_h[idx];
    g_h[idx] = fmaf(z, hold - nn, nn);
}

// ---------------- graph segment offsets --------------------------------------
__global__ void k_seg_zero(int B) {
    int b = threadIdx.x;
    if (b < B) { g_start[b] = 0x7fffffff; g_cnt[b] = 0; }
}
__global__ void k_seg_scan(const int* __restrict__ gidx, int N) {
    int n = blockIdx.x * blockDim.x + threadIdx.x;
    if (n >= N) return;
    int g = gidx[n];
    atomicMin(&g_start[g], n);
    atomicAdd(&g_cnt[g], 1);
}

// ---------------- fused Set2Set (3 steps) + FC head: one block per graph -----
__global__ void k_s2s_all(const float* __restrict__ bih, const float* __restrict__ bhh,
                          const float* __restrict__ fc1_w, const float* __restrict__ fc1_b,
                          const float* __restrict__ fc2_w, const float* __restrict__ fc2_b,
                          float* __restrict__ out) {
    int b = blockIdx.x, t = threadIdx.x;
    __shared__ float q_sh[128], h_sh[64], lc_sh[64], gates[256], red[256], rpart[4][64];
    if (t < 128) q_sh[t] = 0.f;
    if (t < 64) { h_sh[t] = 0.f; lc_sh[t] = 0.f; }
    int s = g_start[b], c = g_cnt[b];
    if (s == 0x7fffffff) s = 0;
    __syncthreads();
    for (int step = 0; step < 3; step++) {
        float acc = bih[t] + bhh[t];
        #pragma unroll 8
        for (int k = 0; k < 128; k++) acc = fmaf(q_sh[k], g_s2s_wihT[k * 256 + t], acc);
        #pragma unroll 8
        for (int k = 0; k < 64; k++) acc = fmaf(h_sh[k], g_s2s_whhT[k * 256 + t], acc);
        gates[t] = acc;
        __syncthreads();
        if (t < 64) {
            float ig = sigf(gates[t]), fg = sigf(gates[64 + t]);
            float gg = tanhf(gates[128 + t]), og = sigf(gates[192 + t]);
            float cc = fmaf(fg, lc_sh[t], ig * gg);
            lc_sh[t] = cc;
            h_sh[t] = og * tanhf(cc);
        }
        __syncthreads();
        float lmax = -CUDART_INF_F;
        for (int n = s + t; n < s + c; n += 256) {
            const float* hp = &g_h[(size_t)n * DIM];
            float d = 0.f;
            #pragma unroll 8
            for (int k = 0; k < DIM; k++) d = fmaf(hp[k], h_sh[k], d);
            g_e[n] = d;
            lmax = fmaxf(lmax, d);
        }
        red[t] = lmax;
        __syncthreads();
        for (int off = 128; off > 0; off >>= 1) {
            if (t < off) red[t] = fmaxf(red[t], red[t + off]);
            __syncthreads();
        }
        float emax = red[0];
        __syncthreads();
        float lsum = 0.f;
        for (int n = s + t; n < s + c; n += 256) lsum += expf(g_e[n] - emax);
        red[t] = lsum;
        __syncthreads();
        for (int off = 128; off > 0; off >>= 1) {
            if (t < off) red[t] += red[t + off];
            __syncthreads();
        }
        float inv = red[0] > 0.f ? 1.f / red[0] : 0.f;
        __syncthreads();
        int d = t & 63, sub = t >> 6;
        float acc2 = 0.f;
        for (int n = s + sub; n < s + c; n += 4)
            acc2 = fmaf(expf(g_e[n] - emax), g_h[(size_t)n * DIM + d], acc2);
        rpart[sub][d] = acc2;
        __syncthreads();
        if (t < 64) {
            q_sh[64 + t] = (rpart[0][t] + rpart[1][t] + rpart[2][t] + rpart[3][t]) * inv;
            q_sh[t] = h_sh[t];
        }
        __syncthreads();
    }
    if (t < 64) {
        float acc = fc1_b[t];
        #pragma unroll 8
        for (int k = 0; k < 128; k++) acc = fmaf(q_sh[k], fc1_w[k * DIM + t], acc);
        red[t] = fmaxf(acc, 0.f) * fc2_w[t];
    }
    __syncthreads();
    for (int off = 32; off > 0; off >>= 1) {
        if (t < off) red[t] += red[t + off];
        __syncthreads();
    }
    if (t == 0) out[b] = red[0] + fc2_b[0];
}

// ---------------- launch -----------------------------------------------------
extern "C" void kernel_launch(void* const* d_in, const int* in_sizes, int n_in,
                              void* d_out, int out_size) {
    const int N = in_sizes[0] / 30;
    const int E = in_sizes[1] / 11;
    const int B = out_size;

    const float* nf   = (const float*)d_in[0];
    const float* ef   = (const float*)d_in[1];
    const int*   ei   = (const int*)d_in[2];
    const int*   gidx = (const int*)d_in[3];
    int wb = (in_sizes[4] == 1) ? 5 : 4;
    const float* lin0_w  = (const float*)d_in[wb + 0];
    const float* lin0_b  = (const float*)d_in[wb + 1];
    const float* enn_w1  = (const float*)d_in[wb + 2];
    const float* enn_b1  = (const float*)d_in[wb + 3];
    const float* enn_w2  = (const float*)d_in[wb + 4];
    const float* enn_b2  = (const float*)d_in[wb + 5];
    const float* conv_b  = (const float*)d_in[wb + 6];
    const float* gru_wih = (const float*)d_in[wb + 7];
    const float* gru_whh = (const float*)d_in[wb + 8];
    const float* gru_bih = (const float*)d_in[wb + 9];
    const float* gru_bhh = (const float*)d_in[wb + 10];
    const float* s2s_wih = (const float*)d_in[wb + 11];
    const float* s2s_whh = (const float*)d_in[wb + 12];
    const float* s2s_bih = (const float*)d_in[wb + 13];
    const float* s2s_bhh = (const float*)d_in[wb + 14];
    const float* fc1_w   = (const float*)d_in[wb + 15];
    const float* fc1_b   = (const float*)d_in[wb + 16];
    const float* fc2_w   = (const float*)d_in[wb + 17];
    const float* fc2_b   = (const float*)d_in[wb + 18];
    float* out = (float*)d_out;

    float *p_swihT, *p_swhhT, *p_gbias, *p_gates;
    unsigned *p_ap, *p_bp, *p_xp, *p_gp;
    __half *p_ew;
    cudaGetSymbolAddress((void**)&p_swihT, g_s2s_wihT);
    cudaGetSymbolAddress((void**)&p_swhhT, g_s2s_whhT);
    cudaGetSymbolAddress((void**)&p_ap, g_apack);
    cudaGetSymbolAddress((void**)&p_bp, g_bpack);
    cudaGetSymbolAddress((void**)&p_xp, g_xpack);
    cudaGetSymbolAddress((void**)&p_gp, g_gpack);
    cudaGetSymbolAddress((void**)&p_gbias, g_gbias);
    cudaGetSymbolAddress((void**)&p_gates, g_gates);
    cudaGetSymbolAddress((void**)&p_ew, g_ew16);
    int* p_deg; cudaGetSymbolAddress((void**)&p_deg, g_deg);

    // 1-3 prep; launch 4 = big GEMM (capture target this round)
    {
        int total = E * 64 + 128 * 4096;
        k_prep_all<<<(total + 255) / 256, 256>>>(ef, enn_w1, enn_b1, enn_w2, E);
    }
    k_prep_gruw<<<(128 * 256 + 255) / 256, 256>>>(gru_wih, gru_whh, gru_bih, gru_bhh);
    k_lin0<<<(N * DIM + 255) / 256, 256>>>(nf, lin0_w, lin0_b, N);
    {
        dim3 grid(4096 / 128, (E + 127) / 128);
        k_gemm_frag<512, __half><<<grid, 256>>>(p_ap, p_bp, enn_b2, p_ew, E);
    }

    // degrees
    k_zero_i<<<(N + 255) / 256, 256>>>(p_deg, N);
    k_count<<<(E + 255) / 256, 256>>>(ei, E);
    k_invdeg<<<(N + 255) / 256, 256>>>(N);

    // 3 message-passing + GRU iterations (GRU = xpack + GEMM + combine)
    dim3 ggrid(256 / 128, (N + 127) / 128);
    for (int it = 0; it < 3; it++) {
        k_msg<<<(E + 7) / 8, 256>>>(ei, E);
        k_xpack<<<(N * 64 + 255) / 256, 256>>>(conv_b, N);
        k_gemm_frag<32, float><<<ggrid, 256>>>(p_xp, p_gp, p_gbias, p_gates, N);
        k_gru_combine<<<(N * DIM + 255) / 256, 256>>>(N);
    }

    // Set2Set + FC head
    k_transpose<<<(256 * 128 + 255) / 256, 256>>>(p_swihT, s2s_wih, 256, 128);
    k_transpose<<<(256 * 64 + 255) / 256, 256>>>(p_swhhT, s2s_whh, 256, 64);
    k_seg_zero<<<1, 128>>>(B);
    k_seg_scan<<<(N + 255) / 256, 256>>>(gidx, N);
    k_s2s_all<<<B, 256>>>(s2s_bih, s2s_bhh, fc1_w, fc1_b, fc2_w, fc2_b, out);
}